// round 14
// baseline (speedup 1.0000x reference)
#include <cuda_runtime.h>
#include <cstdint>
#include <cstring>
#include <cmath>

#define NE 200000
#define NA 20000
#define KC 32

// ---------------------------------------------------------------------------
// Pooled scratch (concat layout): L0 [NA][1][96], L1 [NA][3][128], L2 [NA][5][128]
// ---------------------------------------------------------------------------
__device__ __align__(16) float g_pool0[NA * 96];
__device__ __align__(16) float g_pool1[NA * 3 * 128];
__device__ __align__(16) float g_pool2[NA * 5 * 128];

// CSR over centers
__device__ int g_count[NA];
__device__ int g_off[NA];
__device__ int g_cursor[NA];
__device__ int g_eid[NE];

// CG constants passed by value (2460 B < 4KB param limit)
struct CgParam { float v[615]; };

// ---------------------------------------------------------------------------
// Host-side bit-exact replication of np.random.default_rng(42).normal(...)
// ---------------------------------------------------------------------------
namespace cgen {

typedef unsigned __int128 u128;

struct Pcg64 {
    u128 state, inc;
    uint64_t next() {
        const u128 MUL = (((u128)0x2360ed051fc65da4ULL) << 64) | 0x4385df649fccf645ULL;
        state = state * MUL + inc;
        uint64_t hi = (uint64_t)(state >> 64);
        uint64_t lo = (uint64_t)state;
        uint64_t v  = hi ^ lo;
        unsigned rot = (unsigned)(state >> 122);
        return (v >> rot) | (v << ((64u - rot) & 63u));
    }
    double nextd() { return (double)(next() >> 11) * (1.0 / 9007199254740992.0); }
};

static float    h_cg[615];
static CgParam  h_cgp;

struct Init {
    uint64_t zki[256];
    double   zwi[256], zfi[256];
    Pcg64    g;

    double znorm() {
        const double NOR_R = 3.6541528853610088;
        const double NOR_INV_R = 0.27366123732975828;
        for (;;) {
            uint64_t r = g.next();
            int idx = (int)(r & 0xff);
            r >>= 8;
            int sign = (int)(r & 1);
            uint64_t rabs = (r >> 1) & 0x000fffffffffffffULL;
            double x = (double)rabs * zwi[idx];
            if (sign) x = -x;
            if (rabs < zki[idx]) return x;
            if (idx == 0) {
                double xx, yy;
                do {
                    xx = -NOR_INV_R * std::log1p(-g.nextd());
                    yy = -std::log1p(-g.nextd());
                } while (yy + yy <= xx * xx);
                return ((rabs >> 8) & 1) ? -(NOR_R + xx) : NOR_R + xx;
            } else {
                if ((zfi[idx - 1] - zfi[idx]) * g.nextd() + zfi[idx] <
                    std::exp(-0.5 * x * x))
                    return x;
            }
        }
    }

    Init() {
        // ---- SeedSequence(42), pool_size=4 ----
        uint32_t pool[4];
        uint32_t hc = 0x43b0d7e5u;
        auto hashmix = [&hc](uint32_t v) -> uint32_t {
            v ^= hc; hc *= 0x931e8875u; v *= hc; v ^= v >> 16; return v;
        };
        auto mix = [](uint32_t x, uint32_t y) -> uint32_t {
            uint32_t r = x * 0xca01f9ddu - y * 0x4973f715u; r ^= r >> 16; return r;
        };
        pool[0] = hashmix(42u);
        pool[1] = hashmix(0u);
        pool[2] = hashmix(0u);
        pool[3] = hashmix(0u);
        for (int s = 0; s < 4; s++)
            for (int d = 0; d < 4; d++)
                if (s != d) pool[d] = mix(pool[d], hashmix(pool[s]));

        // ---- generate_state(4, uint64) ----
        uint32_t hc2 = 0x8b51f9ddu;
        uint32_t st32[8];
        for (int i = 0; i < 8; i++) {
            uint32_t v = pool[i & 3];
            v ^= hc2; hc2 *= 0x58f38dedu; v *= hc2; v ^= v >> 16;
            st32[i] = v;
        }
        uint64_t s64[4];
        for (int i = 0; i < 4; i++)
            s64[i] = (uint64_t)st32[2 * i] | ((uint64_t)st32[2 * i + 1] << 32);

        // ---- PCG64 seeding ----
        u128 initstate = (((u128)s64[0]) << 64) | s64[1];
        u128 initseq   = (((u128)s64[2]) << 64) | s64[3];
        const u128 MUL = (((u128)0x2360ed051fc65da4ULL) << 64) | 0x4385df649fccf645ULL;
        g.inc = (initseq << 1) | 1;
        g.state = 0;
        g.state = g.state * MUL + g.inc;
        g.state += initstate;
        g.state = g.state * MUL + g.inc;

        // ---- ziggurat tables ----
        const double r = 3.6541528853610088;
        const double M52 = 4503599627370496.0;
        double f_r = std::exp(-0.5 * r * r);
        double V = r * f_r + 1.2533141373155003 * std::erfc(r * 0.7071067811865476);
        double q = V / f_r;
        zki[0] = (uint64_t)((r / q) * M52);
        zki[1] = 0;
        zwi[0] = q / M52; zwi[255] = r / M52;
        zfi[0] = 1.0;     zfi[255] = f_r;
        double dn = r, tn = r;
        for (int i = 254; i >= 1; i--) {
            dn = std::sqrt(-2.0 * std::log(V / dn + std::exp(-0.5 * dn * dn)));
            zki[i + 1] = (uint64_t)((dn / tn) * M52);
            tn = dn;
            zfi[i] = std::exp(-0.5 * dn * dn);
            zwi[i] = dn / M52;
        }

        // ---- draw all 15 CG tensors in dict order ----
        int pos = 0;
        for (int l1 = 0; l1 <= 2; l1++)
            for (int l2 = 0; l2 <= 2; l2++) {
                int lo = l1 > l2 ? l1 - l2 : l2 - l1;
                int hi = (l1 + l2 < 2) ? (l1 + l2) : 2;
                for (int L = lo; L <= hi; L++) {
                    int n = (2 * l1 + 1) * (2 * l2 + 1) * (2 * L + 1);
                    for (int i = 0; i < n; i++)
                        h_cg[pos++] = (float)(znorm() * 0.3);
                }
            }
        std::memcpy(h_cgp.v, h_cg, sizeof(h_cg));
    }
};
static Init g_init;

} // namespace cgen

// ---------------------------------------------------------------------------
// CSR build kernels
// ---------------------------------------------------------------------------
__global__ void zero_counts_kernel() {
    int i = blockIdx.x * blockDim.x + threadIdx.x;
    if (i < NA) g_count[i] = 0;
}

__global__ void hist_kernel(const int* __restrict__ centers) {
    int e = blockIdx.x * blockDim.x + threadIdx.x;
    if (e < NE) atomicAdd(&g_count[centers[e]], 1);
}

__global__ void scan_kernel() {
    __shared__ int s[1024];
    const int t = threadIdx.x;
    const int CH = 20;
    int base = t * CH;
    int loc[CH];
    int sum = 0;
#pragma unroll
    for (int i = 0; i < CH; i++) {
        int idx = base + i;
        int c = (idx < NA) ? g_count[idx] : 0;
        loc[i] = sum;
        sum += c;
    }
    s[t] = sum;
    __syncthreads();
    for (int d = 1; d < 1024; d <<= 1) {
        int v = (t >= d) ? s[t - d] : 0;
        __syncthreads();
        s[t] += v;
        __syncthreads();
    }
    int excl = (t == 0) ? 0 : s[t - 1];
#pragma unroll
    for (int i = 0; i < CH; i++) {
        int idx = base + i;
        if (idx < NA) {
            int o = excl + loc[i];
            g_off[idx] = o;
            g_cursor[idx] = o;
        }
    }
}

__global__ void scatter_kernel(const int* __restrict__ centers) {
    int e = blockIdx.x * blockDim.x + threadIdx.x;
    if (e < NE) {
        int p = atomicAdd(&g_cursor[centers[e]], 1);
        g_eid[p] = e;
    }
}

// ---------------------------------------------------------------------------
// Per-edge value bundle (lane-private): 3 radial, 9 feat, 1 sh-lane slot
// ---------------------------------------------------------------------------
struct EVals {
    float shv;              // lane k<9 holds sh value #k for this edge
    float r0, r1, r2;
    float f0, f1[3], f2[5];
};

__device__ __forceinline__ void load_evals(
    EVals& v, int e, int nb, int k,
    const float* __restrict__ radial,
    const float* __restrict__ sh0, const float* __restrict__ sh1,
    const float* __restrict__ sh2,
    const float* __restrict__ feat0, const float* __restrict__ feat1,
    const float* __restrict__ feat2)
{
    v.shv = (k == 0) ? __ldg(sh0 + e)
          : (k < 4)  ? __ldg(sh1 + 3 * e + k - 1)
          : (k < 9)  ? __ldg(sh2 + 5 * e + k - 4) : 0.f;
    v.r0 = __ldg(radial + (size_t)e * KC + k);
    v.r1 = __ldg(radial + (size_t)NE * KC + (size_t)e * KC + k);
    v.r2 = __ldg(radial + 2 * (size_t)NE * KC + (size_t)e * KC + k);
    v.f0 = __ldg(feat0 + (size_t)nb * KC + k);
#pragma unroll
    for (int a = 0; a < 3; a++) v.f1[a] = __ldg(feat1 + ((size_t)nb * 3 + a) * KC + k);
#pragma unroll
    for (int a = 0; a < 5; a++) v.f2[a] = __ldg(feat2 + ((size_t)nb * 5 + a) * KC + k);
}

// ---------------------------------------------------------------------------
// Gather kernel: warp = atom, lane = channel k. 128-thread blocks (4 atoms).
// Streamed pair products (no P/q arrays) to cut register pressure;
// 2-deep index pipeline + 1-deep value prefetch; sh via shuffle broadcast.
// ---------------------------------------------------------------------------
__global__ void __launch_bounds__(128) gather_kernel(
    CgParam cgp,
    const float* __restrict__ radial,
    const float* __restrict__ sh0, const float* __restrict__ sh1,
    const float* __restrict__ sh2,
    const float* __restrict__ feat0, const float* __restrict__ feat1,
    const float* __restrict__ feat2,
    const int* __restrict__ neighbors)
{
    __shared__ float scg[616];
    for (int i = threadIdx.x; i < 615; i += 128) scg[i] = cgp.v[i];
    __syncthreads();

    const int k = threadIdx.x & 31;
    const int atom = blockIdx.x * 4 + (threadIdx.x >> 5);
    if (atom >= NA) return;

    const int beg = g_off[atom];
    const int end = beg + g_count[atom];

    float A00 = 0.f, A01 = 0.f, A02 = 0.f;
    float B[12], C[20];
#pragma unroll
    for (int i = 0; i < 12; i++) B[i] = 0.f;
#pragma unroll
    for (int i = 0; i < 20; i++) C[i] = 0.f;

    // ---- pipeline prologue ----
    int e1 = 0, nb1 = 0;          // indices for it+1
    EVals cur;
    if (beg < end) {
        int e0  = __ldg(g_eid + beg);
        int nb0 = __ldg(neighbors + e0);
        load_evals(cur, e0, nb0, k, radial, sh0, sh1, sh2, feat0, feat1, feat2);
        if (beg + 1 < end) {
            e1  = __ldg(g_eid + beg + 1);
            nb1 = __ldg(neighbors + e1);
        }
    }

    for (int it = beg; it < end; it++) {
        // ---- issue index chain for it+2 ----
        int e2 = e1, nb2 = nb1;
        if (it + 2 < end) {
            e2  = __ldg(g_eid + it + 2);
            nb2 = __ldg(neighbors + e2);
        }
        // ---- prefetch values for it+1 (indices already resolved) ----
        EVals nxt = cur;
        if (it + 1 < end)
            load_evals(nxt, e1, nb1, k, radial, sh0, sh1, sh2, feat0, feat1, feat2);

        // ---- broadcast sh values from lanes 0..8 ----
        const float s0 = __shfl_sync(0xffffffffu, cur.shv, 0);
        float t11[3], t12[5];
#pragma unroll
        for (int a = 0; a < 3; a++)
            t11[a] = __shfl_sync(0xffffffffu, cur.shv, 1 + a) * cur.r1;
#pragma unroll
        for (int a = 0; a < 5; a++)
            t12[a] = __shfl_sync(0xffffffffu, cur.shv, 4 + a) * cur.r2;
        const float t10 = s0 * cur.r0;

        const float f0 = cur.f0;

        // ---- streamed contractions (no materialized product arrays) ----
        // (0,0,0)@0
        A00 = fmaf(scg[0], t10 * f0, A00);

        // P11 stream: (1,1,0)@44 -> A01, (1,1,2)@80 -> C[5..9]
#pragma unroll
        for (int a = 0; a < 3; a++)
#pragma unroll
            for (int b = 0; b < 3; b++) {
                const float p = t11[a] * cur.f1[b];
                const int i = a * 3 + b;
                A01 = fmaf(p, scg[44 + i], A01);
#pragma unroll
                for (int M = 0; M < 5; M++)
                    C[5 + M] = fmaf(p, scg[80 + i * 5 + M], C[5 + M]);
            }

        // P22 stream: (2,2,0)@390 -> A02, (2,2,2)@490 -> C[15..19]
#pragma unroll
        for (int a = 0; a < 5; a++)
#pragma unroll
            for (int b = 0; b < 5; b++) {
                const float p = t12[a] * cur.f2[b];
                const int i = a * 5 + b;
                A02 = fmaf(p, scg[390 + i], A02);
#pragma unroll
                for (int M = 0; M < 5; M++)
                    C[15 + M] = fmaf(p, scg[490 + i * 5 + M], C[15 + M]);
            }

        // (0,1,1)@1 -> B[0..2]
#pragma unroll
        for (int b = 0; b < 3; b++) {
            const float p = t10 * cur.f1[b];
#pragma unroll
            for (int M = 0; M < 3; M++)
                B[M] = fmaf(p, scg[1 + b * 3 + M], B[M]);
        }
        // (1,0,1)@35 -> B[3..5]
#pragma unroll
        for (int a = 0; a < 3; a++) {
            const float p = t11[a] * f0;
#pragma unroll
            for (int M = 0; M < 3; M++)
                B[3 + M] = fmaf(p, scg[35 + a * 3 + M], B[3 + M]);
        }
        // (1,2,1)@125 -> B[6..8]
#pragma unroll
        for (int a = 0; a < 3; a++)
#pragma unroll
            for (int b = 0; b < 5; b++) {
                const float p = t11[a] * cur.f2[b];
                const int i = a * 5 + b;
#pragma unroll
                for (int M = 0; M < 3; M++)
                    B[6 + M] = fmaf(p, scg[125 + i * 3 + M], B[6 + M]);
            }
        // (2,1,1)@270 -> B[9..11]
#pragma unroll
        for (int a = 0; a < 5; a++)
#pragma unroll
            for (int b = 0; b < 3; b++) {
                const float p = t12[a] * cur.f1[b];
                const int i = a * 3 + b;
#pragma unroll
                for (int M = 0; M < 3; M++)
                    B[9 + M] = fmaf(p, scg[270 + i * 3 + M], B[9 + M]);
            }
        // (0,2,2)@10 -> C[0..4]
#pragma unroll
        for (int b = 0; b < 5; b++) {
            const float p = t10 * cur.f2[b];
#pragma unroll
            for (int M = 0; M < 5; M++)
                C[M] = fmaf(p, scg[10 + b * 5 + M], C[M]);
        }
        // (2,0,2)@245 -> C[10..14]
#pragma unroll
        for (int a = 0; a < 5; a++) {
            const float p = t12[a] * f0;
#pragma unroll
            for (int M = 0; M < 5; M++)
                C[10 + M] = fmaf(p, scg[245 + a * 5 + M], C[10 + M]);
        }

        // ---- rotate pipeline ----
        cur = nxt;
        e1 = e2; nb1 = nb2;
    }

    // ---- write pooled rows (coalesced, no atomics) ----
    float* p0 = g_pool0 + (size_t)atom * 96 + k;
    p0[0]  = A00;
    p0[32] = A01;
    p0[64] = A02;

    float* p1 = g_pool1 + (size_t)atom * 384 + k;
#pragma unroll
    for (int M = 0; M < 3; M++) {
        p1[M * 128 + 0]  = B[0 + M];
        p1[M * 128 + 32] = B[3 + M];
        p1[M * 128 + 64] = B[6 + M];
        p1[M * 128 + 96] = B[9 + M];
    }

    float* p2 = g_pool2 + (size_t)atom * 640 + k;
#pragma unroll
    for (int M = 0; M < 5; M++) {
        p2[M * 128 + 0]  = C[0 + M];
        p2[M * 128 + 32] = C[5 + M];
        p2[M * 128 + 64] = C[10 + M];
        p2[M * 128 + 96] = C[15 + M];
    }
}

// ---------------------------------------------------------------------------
// Atom kernel: per-atom linear + bias, *0.1, + residual feat
// ---------------------------------------------------------------------------
__global__ void __launch_bounds__(288) atom_kernel(
    const float* __restrict__ feat0, const float* __restrict__ feat1,
    const float* __restrict__ feat2,
    const float* __restrict__ W0, const float* __restrict__ b0,
    const float* __restrict__ W1, const float* __restrict__ b1,
    const float* __restrict__ W2, const float* __restrict__ b2,
    float* __restrict__ out)
{
    __shared__ __align__(16) float wt0[32 * 100];
    __shared__ __align__(16) float wt1[32 * 132];
    __shared__ __align__(16) float wt2[32 * 132];
    __shared__ float bsh[96];

    for (int i = threadIdx.x; i < 96 * 32; i += 288)
        wt0[(i & 31) * 100 + (i >> 5)] = W0[i];
    for (int i = threadIdx.x; i < 128 * 32; i += 288)
        wt1[(i & 31) * 132 + (i >> 5)] = W1[i];
    for (int i = threadIdx.x; i < 128 * 32; i += 288)
        wt2[(i & 31) * 132 + (i >> 5)] = W2[i];
    if (threadIdx.x < 32) {
        bsh[threadIdx.x]      = b0[threadIdx.x];
        bsh[32 + threadIdx.x] = b1[threadIdx.x];
        bsh[64 + threadIdx.x] = b2[threadIdx.x];
    }
    __syncthreads();

    const int w = threadIdx.x >> 5;
    const int k = threadIdx.x & 31;

    for (int atom = blockIdx.x; atom < NA; atom += gridDim.x) {
        float acc = 0.f;
        if (w == 0) {
            const float4* pr = reinterpret_cast<const float4*>(g_pool0 + (size_t)atom * 96);
            const float4* wr = reinterpret_cast<const float4*>(wt0 + k * 100);
#pragma unroll
            for (int j = 0; j < 24; j++) {
                float4 p = pr[j], wv = wr[j];
                acc += p.x * wv.x + p.y * wv.y + p.z * wv.z + p.w * wv.w;
            }
            int o = atom * 32 + k;
            out[o] = (acc + bsh[k]) * 0.1f + feat0[o];
        } else if (w <= 3) {
            int M = w - 1;
            const float4* pr = reinterpret_cast<const float4*>(g_pool1 + ((size_t)atom * 3 + M) * 128);
            const float4* wr = reinterpret_cast<const float4*>(wt1 + k * 132);
#pragma unroll
            for (int j = 0; j < 32; j++) {
                float4 p = pr[j], wv = wr[j];
                acc += p.x * wv.x + p.y * wv.y + p.z * wv.z + p.w * wv.w;
            }
            int o = (atom * 3 + M) * 32 + k;
            out[NA * 32 + o] = (acc + bsh[32 + k]) * 0.1f + feat1[o];
        } else {
            int M = w - 4;
            const float4* pr = reinterpret_cast<const float4*>(g_pool2 + ((size_t)atom * 5 + M) * 128);
            const float4* wr = reinterpret_cast<const float4*>(wt2 + k * 132);
#pragma unroll
            for (int j = 0; j < 32; j++) {
                float4 p = pr[j], wv = wr[j];
                acc += p.x * wv.x + p.y * wv.y + p.z * wv.z + p.w * wv.w;
            }
            int o = (atom * 5 + M) * 32 + k;
            out[NA * 32 + NA * 96 + o] = (acc + bsh[64 + k]) * 0.1f + feat2[o];
        }
    }
}

// ---------------------------------------------------------------------------
// Launcher
// ---------------------------------------------------------------------------
extern "C" void kernel_launch(void* const* d_in, const int* in_sizes, int n_in,
                              void* d_out, int out_size) {
    (void)in_sizes; (void)n_in; (void)out_size;
    const float* radial = (const float*)d_in[0];
    const float* sh0    = (const float*)d_in[1];
    const float* sh1    = (const float*)d_in[2];
    const float* sh2    = (const float*)d_in[3];
    const float* feat0  = (const float*)d_in[4];
    const float* feat1  = (const float*)d_in[5];
    const float* feat2  = (const float*)d_in[6];
    const float* W0     = (const float*)d_in[7];
    const float* b0     = (const float*)d_in[8];
    const float* W1     = (const float*)d_in[9];
    const float* b1     = (const float*)d_in[10];
    const float* W2     = (const float*)d_in[11];
    const float* b2     = (const float*)d_in[12];
    const int* centers   = (const int*)d_in[13];
    const int* neighbors = (const int*)d_in[14];
    float* out = (float*)d_out;

    // CSR build over centers
    zero_counts_kernel<<<(NA + 255) / 256, 256>>>();
    hist_kernel<<<(NE + 255) / 256, 256>>>(centers);
    scan_kernel<<<1, 1024>>>();
    scatter_kernel<<<(NE + 255) / 256, 256>>>(centers);

    // gather: warp per atom, 4 atoms per 128-thread block
    gather_kernel<<<NA / 4, 128>>>(cgen::h_cgp, radial, sh0, sh1, sh2,
                                   feat0, feat1, feat2, neighbors);

    atom_kernel<<<1184, 288>>>(feat0, feat1, feat2,
                               W0, b0, W1, b1, W2, b2, out);
}

// round 15
// speedup vs baseline: 1.0001x; 1.0001x over previous
#include <cuda_runtime.h>
#include <cstdint>
#include <cstring>
#include <cmath>

#define NE 200000
#define NA 20000
#define KC 32

// ---------------------------------------------------------------------------
// Pooled scratch (concat layout): L0 [NA][1][96], L1 [NA][3][128], L2 [NA][5][128]
// ---------------------------------------------------------------------------
__device__ __align__(16) float g_pool0[NA * 96];
__device__ __align__(16) float g_pool1[NA * 3 * 128];
__device__ __align__(16) float g_pool2[NA * 5 * 128];

// CSR over centers (g_count zero-initialized at module load; gather re-zeroes it)
__device__ int g_count[NA];
__device__ int g_off[NA];
__device__ int g_cursor[NA];
__device__ int g_eid[NE];

// CG constants passed by value (2460 B < 4KB param limit)
struct CgParam { float v[615]; };

// ---------------------------------------------------------------------------
// Host-side bit-exact replication of np.random.default_rng(42).normal(...)
// ---------------------------------------------------------------------------
namespace cgen {

typedef unsigned __int128 u128;

struct Pcg64 {
    u128 state, inc;
    uint64_t next() {
        const u128 MUL = (((u128)0x2360ed051fc65da4ULL) << 64) | 0x4385df649fccf645ULL;
        state = state * MUL + inc;
        uint64_t hi = (uint64_t)(state >> 64);
        uint64_t lo = (uint64_t)state;
        uint64_t v  = hi ^ lo;
        unsigned rot = (unsigned)(state >> 122);
        return (v >> rot) | (v << ((64u - rot) & 63u));
    }
    double nextd() { return (double)(next() >> 11) * (1.0 / 9007199254740992.0); }
};

static float    h_cg[615];
static CgParam  h_cgp;

struct Init {
    uint64_t zki[256];
    double   zwi[256], zfi[256];
    Pcg64    g;

    double znorm() {
        const double NOR_R = 3.6541528853610088;
        const double NOR_INV_R = 0.27366123732975828;
        for (;;) {
            uint64_t r = g.next();
            int idx = (int)(r & 0xff);
            r >>= 8;
            int sign = (int)(r & 1);
            uint64_t rabs = (r >> 1) & 0x000fffffffffffffULL;
            double x = (double)rabs * zwi[idx];
            if (sign) x = -x;
            if (rabs < zki[idx]) return x;
            if (idx == 0) {
                double xx, yy;
                do {
                    xx = -NOR_INV_R * std::log1p(-g.nextd());
                    yy = -std::log1p(-g.nextd());
                } while (yy + yy <= xx * xx);
                return ((rabs >> 8) & 1) ? -(NOR_R + xx) : NOR_R + xx;
            } else {
                if ((zfi[idx - 1] - zfi[idx]) * g.nextd() + zfi[idx] <
                    std::exp(-0.5 * x * x))
                    return x;
            }
        }
    }

    Init() {
        // ---- SeedSequence(42), pool_size=4 ----
        uint32_t pool[4];
        uint32_t hc = 0x43b0d7e5u;
        auto hashmix = [&hc](uint32_t v) -> uint32_t {
            v ^= hc; hc *= 0x931e8875u; v *= hc; v ^= v >> 16; return v;
        };
        auto mix = [](uint32_t x, uint32_t y) -> uint32_t {
            uint32_t r = x * 0xca01f9ddu - y * 0x4973f715u; r ^= r >> 16; return r;
        };
        pool[0] = hashmix(42u);
        pool[1] = hashmix(0u);
        pool[2] = hashmix(0u);
        pool[3] = hashmix(0u);
        for (int s = 0; s < 4; s++)
            for (int d = 0; d < 4; d++)
                if (s != d) pool[d] = mix(pool[d], hashmix(pool[s]));

        // ---- generate_state(4, uint64) ----
        uint32_t hc2 = 0x8b51f9ddu;
        uint32_t st32[8];
        for (int i = 0; i < 8; i++) {
            uint32_t v = pool[i & 3];
            v ^= hc2; hc2 *= 0x58f38dedu; v *= hc2; v ^= v >> 16;
            st32[i] = v;
        }
        uint64_t s64[4];
        for (int i = 0; i < 4; i++)
            s64[i] = (uint64_t)st32[2 * i] | ((uint64_t)st32[2 * i + 1] << 32);

        // ---- PCG64 seeding ----
        u128 initstate = (((u128)s64[0]) << 64) | s64[1];
        u128 initseq   = (((u128)s64[2]) << 64) | s64[3];
        const u128 MUL = (((u128)0x2360ed051fc65da4ULL) << 64) | 0x4385df649fccf645ULL;
        g.inc = (initseq << 1) | 1;
        g.state = 0;
        g.state = g.state * MUL + g.inc;
        g.state += initstate;
        g.state = g.state * MUL + g.inc;

        // ---- ziggurat tables ----
        const double r = 3.6541528853610088;
        const double M52 = 4503599627370496.0;
        double f_r = std::exp(-0.5 * r * r);
        double V = r * f_r + 1.2533141373155003 * std::erfc(r * 0.7071067811865476);
        double q = V / f_r;
        zki[0] = (uint64_t)((r / q) * M52);
        zki[1] = 0;
        zwi[0] = q / M52; zwi[255] = r / M52;
        zfi[0] = 1.0;     zfi[255] = f_r;
        double dn = r, tn = r;
        for (int i = 254; i >= 1; i--) {
            dn = std::sqrt(-2.0 * std::log(V / dn + std::exp(-0.5 * dn * dn)));
            zki[i + 1] = (uint64_t)((dn / tn) * M52);
            tn = dn;
            zfi[i] = std::exp(-0.5 * dn * dn);
            zwi[i] = dn / M52;
        }

        // ---- draw all 15 CG tensors in dict order ----
        int pos = 0;
        for (int l1 = 0; l1 <= 2; l1++)
            for (int l2 = 0; l2 <= 2; l2++) {
                int lo = l1 > l2 ? l1 - l2 : l2 - l1;
                int hi = (l1 + l2 < 2) ? (l1 + l2) : 2;
                for (int L = lo; L <= hi; L++) {
                    int n = (2 * l1 + 1) * (2 * l2 + 1) * (2 * L + 1);
                    for (int i = 0; i < n; i++)
                        h_cg[pos++] = (float)(znorm() * 0.3);
                }
            }
        std::memcpy(h_cgp.v, h_cg, sizeof(h_cg));
    }
};
static Init g_init;

} // namespace cgen

// ---------------------------------------------------------------------------
// Packed f32x2 helpers (sm_103a)
// ---------------------------------------------------------------------------
typedef unsigned long long u64p;

__device__ __forceinline__ u64p pk2(float lo, float hi) {
    u64p r; asm("mov.b64 %0,{%1,%2};" : "=l"(r) : "f"(lo), "f"(hi)); return r;
}
__device__ __forceinline__ u64p pdup(float x) { return pk2(x, x); }
__device__ __forceinline__ u64p pmul(u64p a, u64p b) {
    u64p r; asm("mul.rn.f32x2 %0,%1,%2;" : "=l"(r) : "l"(a), "l"(b)); return r;
}
__device__ __forceinline__ void pfma(u64p& c, u64p a, u64p b) {
    asm("fma.rn.f32x2 %0,%1,%2,%0;" : "+l"(c) : "l"(a), "l"(b));
}
__device__ __forceinline__ float hsum(u64p a) {
    float x, y; asm("mov.b64 {%0,%1},%2;" : "=f"(x), "=f"(y) : "l"(a)); return x + y;
}

// ---------------------------------------------------------------------------
// CSR build kernels (zeroing of g_count is done by gather's epilogue)
// ---------------------------------------------------------------------------
__global__ void hist_kernel(const int* __restrict__ centers) {
    int e = blockIdx.x * blockDim.x + threadIdx.x;
    if (e < NE) atomicAdd(&g_count[centers[e]], 1);
}

__global__ void scan_kernel() {
    __shared__ int s[1024];
    const int t = threadIdx.x;
    const int CH = 20;
    int base = t * CH;
    int loc[CH];
    int sum = 0;
#pragma unroll
    for (int i = 0; i < CH; i++) {
        int idx = base + i;
        int c = (idx < NA) ? g_count[idx] : 0;
        loc[i] = sum;
        sum += c;
    }
    s[t] = sum;
    __syncthreads();
    for (int d = 1; d < 1024; d <<= 1) {
        int v = (t >= d) ? s[t - d] : 0;
        __syncthreads();
        s[t] += v;
        __syncthreads();
    }
    int excl = (t == 0) ? 0 : s[t - 1];
#pragma unroll
    for (int i = 0; i < CH; i++) {
        int idx = base + i;
        if (idx < NA) {
            int o = excl + loc[i];
            g_off[idx] = o;
            g_cursor[idx] = o;
        }
    }
}

__global__ void scatter_kernel(const int* __restrict__ centers) {
    int e = blockIdx.x * blockDim.x + threadIdx.x;
    if (e < NE) {
        int p = atomicAdd(&g_cursor[centers[e]], 1);
        g_eid[p] = e;
    }
}

// ---------------------------------------------------------------------------
// Per-edge value bundle (lane-private): 3 radial, 9 feat, 1 sh-lane slot
// ---------------------------------------------------------------------------
struct EVals {
    float shv;              // lane k<9 holds sh value #k for this edge
    float r0, r1, r2;
    float f0, f1[3], f2[5];
};

__device__ __forceinline__ void load_evals(
    EVals& v, int e, int nb, int k,
    const float* __restrict__ radial,
    const float* __restrict__ sh0, const float* __restrict__ sh1,
    const float* __restrict__ sh2,
    const float* __restrict__ feat0, const float* __restrict__ feat1,
    const float* __restrict__ feat2)
{
    v.shv = (k == 0) ? __ldg(sh0 + e)
          : (k < 4)  ? __ldg(sh1 + 3 * e + k - 1)
          : (k < 9)  ? __ldg(sh2 + 5 * e + k - 4) : 0.f;
    v.r0 = __ldg(radial + (size_t)e * KC + k);
    v.r1 = __ldg(radial + (size_t)NE * KC + (size_t)e * KC + k);
    v.r2 = __ldg(radial + 2 * (size_t)NE * KC + (size_t)e * KC + k);
    v.f0 = __ldg(feat0 + (size_t)nb * KC + k);
#pragma unroll
    for (int a = 0; a < 3; a++) v.f1[a] = __ldg(feat1 + ((size_t)nb * 3 + a) * KC + k);
#pragma unroll
    for (int a = 0; a < 5; a++) v.f2[a] = __ldg(feat2 + ((size_t)nb * 5 + a) * KC + k);
}

// ---------------------------------------------------------------------------
// Packed-CG pair table layout (226 float2 entries):
//  O110=0(6)  O112=6(30)  O220=36(15)  O222=51(75)  O011=126(6)  O101=132(6)
//  O121=138(27)  O211=165(30)  O022=195(15)  O202=210(15)  O000=225(1)
// ---------------------------------------------------------------------------
__device__ __forceinline__ void pcg_decode(int u, int& lo, int& hi) {
    lo = -1; hi = -1;
    if (u < 6) {                       // (1,1,0): a*2+j ; cg44 idx a*3+b
        int a = u >> 1, j = u & 1, b0 = 2 * j;
        lo = 44 + a * 3 + b0; if (b0 + 1 < 3) hi = lo + 1;
    } else if (u < 36) {               // (1,1,2): (a*2+j)*5+M ; cg80 idx (a*3+b)*5+M
        int t = u - 6, M = t % 5, aj = t / 5, a = aj >> 1, j = aj & 1, b0 = 2 * j;
        lo = 80 + (a * 3 + b0) * 5 + M; if (b0 + 1 < 3) hi = lo + 5;
    } else if (u < 51) {               // (2,2,0): a*3+j ; cg390 idx a*5+b
        int t = u - 36, a = t / 3, j = t % 3, b0 = 2 * j;
        lo = 390 + a * 5 + b0; if (b0 + 1 < 5) hi = lo + 1;
    } else if (u < 126) {              // (2,2,2): (a*3+j)*5+M ; cg490 idx (a*5+b)*5+M
        int t = u - 51, M = t % 5, aj = t / 5, a = aj / 3, j = aj % 3, b0 = 2 * j;
        lo = 490 + (a * 5 + b0) * 5 + M; if (b0 + 1 < 5) hi = lo + 5;
    } else if (u < 132) {              // (0,1,1): j*3+M ; cg1 idx b*3+M
        int t = u - 126, j = t / 3, M = t % 3, b0 = 2 * j;
        lo = 1 + b0 * 3 + M; if (b0 + 1 < 3) hi = lo + 3;
    } else if (u < 138) {              // (1,0,1): j*3+M ; cg35 idx a*3+M (sum over a)
        int t = u - 132, j = t / 3, M = t % 3, a0 = 2 * j;
        lo = 35 + a0 * 3 + M; if (a0 + 1 < 3) hi = lo + 3;
    } else if (u < 165) {              // (1,2,1): (a*3+j)*3+M ; cg125 idx (a*5+b)*3+M
        int t = u - 138, M = t % 3, aj = t / 3, a = aj / 3, j = aj % 3, b0 = 2 * j;
        lo = 125 + (a * 5 + b0) * 3 + M; if (b0 + 1 < 5) hi = lo + 3;
    } else if (u < 195) {              // (2,1,1): (a*2+j)*3+M ; cg270 idx (a*3+b)*3+M
        int t = u - 165, M = t % 3, aj = t / 3, a = aj >> 1, j = aj & 1, b0 = 2 * j;
        lo = 270 + (a * 3 + b0) * 3 + M; if (b0 + 1 < 3) hi = lo + 3;
    } else if (u < 210) {              // (0,2,2): j*5+M ; cg10 idx b*5+M
        int t = u - 195, j = t / 5, M = t % 5, b0 = 2 * j;
        lo = 10 + b0 * 5 + M; if (b0 + 1 < 5) hi = lo + 5;
    } else if (u < 225) {              // (2,0,2): j*5+M ; cg245 idx a*5+M (sum over a)
        int t = u - 210, j = t / 5, M = t % 5, a0 = 2 * j;
        lo = 245 + a0 * 5 + M; if (a0 + 1 < 5) hi = lo + 5;
    } else {                           // (0,0,0)
        lo = 0;
    }
}

// ---------------------------------------------------------------------------
// Gather kernel: warp = atom, lane = channel k. Packed f32x2 contraction.
// 128-thread blocks (4 atoms). 2-deep index pipeline + 1-deep value prefetch.
// Epilogue zeroes g_count[atom] for the next call's histogram.
// ---------------------------------------------------------------------------
__global__ void __launch_bounds__(128) gather_kernel(
    CgParam cgp,
    const float* __restrict__ radial,
    const float* __restrict__ sh0, const float* __restrict__ sh1,
    const float* __restrict__ sh2,
    const float* __restrict__ feat0, const float* __restrict__ feat1,
    const float* __restrict__ feat2,
    const int* __restrict__ neighbors)
{
    __shared__ __align__(8) float2 pcg[226];
    for (int u = threadIdx.x; u < 226; u += 128) {
        int lo, hi;
        pcg_decode(u, lo, hi);
        pcg[u] = make_float2(lo >= 0 ? cgp.v[lo] : 0.f,
                             hi >= 0 ? cgp.v[hi] : 0.f);
    }
    __syncthreads();
    const u64p* PC = reinterpret_cast<const u64p*>(pcg);

    const int k = threadIdx.x & 31;
    const int atom = blockIdx.x * 4 + (threadIdx.x >> 5);
    if (atom >= NA) return;

    const int beg = g_off[atom];
    const int cnt = g_count[atom];
    const int end = beg + cnt;

    // packed accumulators (value = lo + hi at the end)
    u64p A00p = 0, A01p = 0, A02p = 0;
    u64p B0p[3], B3p[3], B6p[3], B9p[3];
    u64p C0p[5], C5p[5], C10p[5], C15p[5];
#pragma unroll
    for (int i = 0; i < 3; i++) { B0p[i] = 0; B3p[i] = 0; B6p[i] = 0; B9p[i] = 0; }
#pragma unroll
    for (int i = 0; i < 5; i++) { C0p[i] = 0; C5p[i] = 0; C10p[i] = 0; C15p[i] = 0; }

    // ---- pipeline prologue ----
    int e1 = 0, nb1 = 0;
    EVals cur;
    if (beg < end) {
        int e0  = __ldg(g_eid + beg);
        int nb0 = __ldg(neighbors + e0);
        load_evals(cur, e0, nb0, k, radial, sh0, sh1, sh2, feat0, feat1, feat2);
        if (beg + 1 < end) {
            e1  = __ldg(g_eid + beg + 1);
            nb1 = __ldg(neighbors + e1);
        }
    }

    for (int it = beg; it < end; it++) {
        // index chain for it+2
        int e2 = e1, nb2 = nb1;
        if (it + 2 < end) {
            e2  = __ldg(g_eid + it + 2);
            nb2 = __ldg(neighbors + e2);
        }
        // value prefetch for it+1
        EVals nxt = cur;
        if (it + 1 < end)
            load_evals(nxt, e1, nb1, k, radial, sh0, sh1, sh2, feat0, feat1, feat2);

        // broadcast sh, build t vectors
        const float t10 = __shfl_sync(0xffffffffu, cur.shv, 0) * cur.r0;
        float t11[3], t12[5];
#pragma unroll
        for (int a = 0; a < 3; a++)
            t11[a] = __shfl_sync(0xffffffffu, cur.shv, 1 + a) * cur.r1;
#pragma unroll
        for (int a = 0; a < 5; a++)
            t12[a] = __shfl_sync(0xffffffffu, cur.shv, 4 + a) * cur.r2;

        // packed operand vectors (zero-padded on odd lengths)
        const u64p T10d = pdup(t10);
        const u64p F0d  = pdup(cur.f0);
        const u64p F1p0 = pk2(cur.f1[0], cur.f1[1]), F1p1 = pk2(cur.f1[2], 0.f);
        const u64p F2p0 = pk2(cur.f2[0], cur.f2[1]);
        const u64p F2p1 = pk2(cur.f2[2], cur.f2[3]);
        const u64p F2p2 = pk2(cur.f2[4], 0.f);
        const u64p T11p0 = pk2(t11[0], t11[1]), T11p1 = pk2(t11[2], 0.f);
        const u64p T12p0 = pk2(t12[0], t12[1]);
        const u64p T12p1 = pk2(t12[2], t12[3]);
        const u64p T12p2 = pk2(t12[4], 0.f);

        // (0,0,0)
        pfma(A00p, pmul(T10d, F0d), PC[225]);

        // P11 cluster: (1,1,0)->A01, (1,1,2)->C5, plus (1,2,1)->B6 (reuses dup)
#pragma unroll
        for (int a = 0; a < 3; a++) {
            const u64p da = pdup(t11[a]);
            const u64p p0 = pmul(da, F1p0);
            const u64p p1 = pmul(da, F1p1);
            pfma(A01p, p0, PC[0 + a * 2 + 0]);
            pfma(A01p, p1, PC[0 + a * 2 + 1]);
#pragma unroll
            for (int M = 0; M < 5; M++) {
                pfma(C5p[M], p0, PC[6 + (a * 2 + 0) * 5 + M]);
                pfma(C5p[M], p1, PC[6 + (a * 2 + 1) * 5 + M]);
            }
            const u64p q0 = pmul(da, F2p0);
            const u64p q1 = pmul(da, F2p1);
            const u64p q2 = pmul(da, F2p2);
#pragma unroll
            for (int M = 0; M < 3; M++) {
                pfma(B6p[M], q0, PC[138 + (a * 3 + 0) * 3 + M]);
                pfma(B6p[M], q1, PC[138 + (a * 3 + 1) * 3 + M]);
                pfma(B6p[M], q2, PC[138 + (a * 3 + 2) * 3 + M]);
            }
        }

        // P22 cluster: (2,2,0)->A02, (2,2,2)->C15, plus (2,1,1)->B9
#pragma unroll
        for (int a = 0; a < 5; a++) {
            const u64p da = pdup(t12[a]);
            const u64p p0 = pmul(da, F2p0);
            const u64p p1 = pmul(da, F2p1);
            const u64p p2 = pmul(da, F2p2);
            pfma(A02p, p0, PC[36 + a * 3 + 0]);
            pfma(A02p, p1, PC[36 + a * 3 + 1]);
            pfma(A02p, p2, PC[36 + a * 3 + 2]);
#pragma unroll
            for (int M = 0; M < 5; M++) {
                pfma(C15p[M], p0, PC[51 + (a * 3 + 0) * 5 + M]);
                pfma(C15p[M], p1, PC[51 + (a * 3 + 1) * 5 + M]);
                pfma(C15p[M], p2, PC[51 + (a * 3 + 2) * 5 + M]);
            }
            const u64p q0 = pmul(da, F1p0);
            const u64p q1 = pmul(da, F1p1);
#pragma unroll
            for (int M = 0; M < 3; M++) {
                pfma(B9p[M], q0, PC[165 + (a * 2 + 0) * 3 + M]);
                pfma(B9p[M], q1, PC[165 + (a * 2 + 1) * 3 + M]);
            }
        }

        // (0,1,1) -> B0
        {
            const u64p p0 = pmul(T10d, F1p0);
            const u64p p1 = pmul(T10d, F1p1);
#pragma unroll
            for (int M = 0; M < 3; M++) {
                pfma(B0p[M], p0, PC[126 + 0 * 3 + M]);
                pfma(B0p[M], p1, PC[126 + 1 * 3 + M]);
            }
        }
        // (1,0,1) -> B3 (pairs over a)
        {
            const u64p p0 = pmul(T11p0, F0d);
            const u64p p1 = pmul(T11p1, F0d);
#pragma unroll
            for (int M = 0; M < 3; M++) {
                pfma(B3p[M], p0, PC[132 + 0 * 3 + M]);
                pfma(B3p[M], p1, PC[132 + 1 * 3 + M]);
            }
        }
        // (0,2,2) -> C0
        {
            const u64p p0 = pmul(T10d, F2p0);
            const u64p p1 = pmul(T10d, F2p1);
            const u64p p2 = pmul(T10d, F2p2);
#pragma unroll
            for (int M = 0; M < 5; M++) {
                pfma(C0p[M], p0, PC[195 + 0 * 5 + M]);
                pfma(C0p[M], p1, PC[195 + 1 * 5 + M]);
                pfma(C0p[M], p2, PC[195 + 2 * 5 + M]);
            }
        }
        // (2,0,2) -> C10 (pairs over a)
        {
            const u64p p0 = pmul(T12p0, F0d);
            const u64p p1 = pmul(T12p1, F0d);
            const u64p p2 = pmul(T12p2, F0d);
#pragma unroll
            for (int M = 0; M < 5; M++) {
                pfma(C10p[M], p0, PC[210 + 0 * 5 + M]);
                pfma(C10p[M], p1, PC[210 + 1 * 5 + M]);
                pfma(C10p[M], p2, PC[210 + 2 * 5 + M]);
            }
        }

        // rotate pipeline
        cur = nxt;
        e1 = e2; nb1 = nb2;
    }

    // ---- write pooled rows (coalesced, no atomics) ----
    float* p0 = g_pool0 + (size_t)atom * 96 + k;
    p0[0]  = hsum(A00p);
    p0[32] = hsum(A01p);
    p0[64] = hsum(A02p);

    float* p1 = g_pool1 + (size_t)atom * 384 + k;
#pragma unroll
    for (int M = 0; M < 3; M++) {
        p1[M * 128 + 0]  = hsum(B0p[M]);
        p1[M * 128 + 32] = hsum(B3p[M]);
        p1[M * 128 + 64] = hsum(B6p[M]);
        p1[M * 128 + 96] = hsum(B9p[M]);
    }

    float* p2 = g_pool2 + (size_t)atom * 640 + k;
#pragma unroll
    for (int M = 0; M < 5; M++) {
        p2[M * 128 + 0]  = hsum(C0p[M]);
        p2[M * 128 + 32] = hsum(C5p[M]);
        p2[M * 128 + 64] = hsum(C10p[M]);
        p2[M * 128 + 96] = hsum(C15p[M]);
    }

    // re-zero count for the next call's histogram
    if (k == 0) g_count[atom] = 0;
}

// ---------------------------------------------------------------------------
// Atom kernel: per-atom linear + bias, *0.1, + residual feat.
// Loop interchange: each weight float4 (LDS) is reused across 4 atoms.
// ---------------------------------------------------------------------------
__global__ void __launch_bounds__(288) atom_kernel(
    const float* __restrict__ feat0, const float* __restrict__ feat1,
    const float* __restrict__ feat2,
    const float* __restrict__ W0, const float* __restrict__ b0,
    const float* __restrict__ W1, const float* __restrict__ b1,
    const float* __restrict__ W2, const float* __restrict__ b2,
    float* __restrict__ out)
{
    __shared__ __align__(16) float wt0[32 * 100];
    __shared__ __align__(16) float wt1[32 * 132];
    __shared__ __align__(16) float wt2[32 * 132];
    __shared__ float bsh[96];

    for (int i = threadIdx.x; i < 96 * 32; i += 288)
        wt0[(i & 31) * 100 + (i >> 5)] = W0[i];
    for (int i = threadIdx.x; i < 128 * 32; i += 288)
        wt1[(i & 31) * 132 + (i >> 5)] = W1[i];
    for (int i = threadIdx.x; i < 128 * 32; i += 288)
        wt2[(i & 31) * 132 + (i >> 5)] = W2[i];
    if (threadIdx.x < 32) {
        bsh[threadIdx.x]      = b0[threadIdx.x];
        bsh[32 + threadIdx.x] = b1[threadIdx.x];
        bsh[64 + threadIdx.x] = b2[threadIdx.x];
    }
    __syncthreads();

    const int w = threadIdx.x >> 5;
    const int k = threadIdx.x & 31;

    for (int g = blockIdx.x; g < NA / 4; g += gridDim.x) {
        const int a0 = g * 4;
        float acc[4] = {0.f, 0.f, 0.f, 0.f};
        if (w == 0) {
            const float4* wr = reinterpret_cast<const float4*>(wt0 + k * 100);
#pragma unroll
            for (int j = 0; j < 24; j++) {
                const float4 wv = wr[j];
#pragma unroll
                for (int t = 0; t < 4; t++) {
                    const float4 p = __ldg(reinterpret_cast<const float4*>(
                        g_pool0 + (size_t)(a0 + t) * 96) + j);
                    acc[t] += p.x * wv.x + p.y * wv.y + p.z * wv.z + p.w * wv.w;
                }
            }
#pragma unroll
            for (int t = 0; t < 4; t++) {
                const int o = (a0 + t) * 32 + k;
                out[o] = (acc[t] + bsh[k]) * 0.1f + __ldg(feat0 + o);
            }
        } else if (w <= 3) {
            const int M = w - 1;
            const float4* wr = reinterpret_cast<const float4*>(wt1 + k * 132);
#pragma unroll
            for (int j = 0; j < 32; j++) {
                const float4 wv = wr[j];
#pragma unroll
                for (int t = 0; t < 4; t++) {
                    const float4 p = __ldg(reinterpret_cast<const float4*>(
                        g_pool1 + ((size_t)(a0 + t) * 3 + M) * 128) + j);
                    acc[t] += p.x * wv.x + p.y * wv.y + p.z * wv.z + p.w * wv.w;
                }
            }
#pragma unroll
            for (int t = 0; t < 4; t++) {
                const int o = ((a0 + t) * 3 + M) * 32 + k;
                out[NA * 32 + o] = (acc[t] + bsh[32 + k]) * 0.1f + __ldg(feat1 + o);
            }
        } else {
            const int M = w - 4;
            const float4* wr = reinterpret_cast<const float4*>(wt2 + k * 132);
#pragma unroll
            for (int j = 0; j < 32; j++) {
                const float4 wv = wr[j];
#pragma unroll
                for (int t = 0; t < 4; t++) {
                    const float4 p = __ldg(reinterpret_cast<const float4*>(
                        g_pool2 + ((size_t)(a0 + t) * 5 + M) * 128) + j);
                    acc[t] += p.x * wv.x + p.y * wv.y + p.z * wv.z + p.w * wv.w;
                }
            }
#pragma unroll
            for (int t = 0; t < 4; t++) {
                const int o = ((a0 + t) * 5 + M) * 32 + k;
                out[NA * 32 + NA * 96 + o] = (acc[t] + bsh[64 + k]) * 0.1f + __ldg(feat2 + o);
            }
        }
    }
}

// ---------------------------------------------------------------------------
// Launcher
// ---------------------------------------------------------------------------
extern "C" void kernel_launch(void* const* d_in, const int* in_sizes, int n_in,
                              void* d_out, int out_size) {
    (void)in_sizes; (void)n_in; (void)out_size;
    const float* radial = (const float*)d_in[0];
    const float* sh0    = (const float*)d_in[1];
    const float* sh1    = (const float*)d_in[2];
    const float* sh2    = (const float*)d_in[3];
    const float* feat0  = (const float*)d_in[4];
    const float* feat1  = (const float*)d_in[5];
    const float* feat2  = (const float*)d_in[6];
    const float* W0     = (const float*)d_in[7];
    const float* b0     = (const float*)d_in[8];
    const float* W1     = (const float*)d_in[9];
    const float* b1     = (const float*)d_in[10];
    const float* W2     = (const float*)d_in[11];
    const float* b2     = (const float*)d_in[12];
    const int* centers   = (const int*)d_in[13];
    const int* neighbors = (const int*)d_in[14];
    float* out = (float*)d_out;

    // CSR build over centers (g_count pre-zeroed by previous gather / static init)
    hist_kernel<<<(NE + 255) / 256, 256>>>(centers);
    scan_kernel<<<1, 1024>>>();
    scatter_kernel<<<(NE + 255) / 256, 256>>>(centers);

    // gather: warp per atom, packed f32x2 contraction
    gather_kernel<<<NA / 4, 128>>>(cgen::h_cgp, radial, sh0, sh1, sh2,
                                   feat0, feat1, feat2, neighbors);

    // atom GEMM: weight reuse across 4 atoms
    atom_kernel<<<1250, 288>>>(feat0, feat1, feat2,
                               W0, b0, W1, b1, W2, b2, out);
}

// round 16
// speedup vs baseline: 1.0575x; 1.0574x over previous
#include <cuda_runtime.h>
#include <cstdint>
#include <cstring>
#include <cmath>

#define NE 200000
#define NA 20000
#define KC 32

// ---------------------------------------------------------------------------
// Pooled scratch (concat layout): L0 [NA][1][96], L1 [NA][3][128], L2 [NA][5][128]
// ---------------------------------------------------------------------------
__device__ __align__(16) float g_pool0[NA * 96];
__device__ __align__(16) float g_pool1[NA * 3 * 128];
__device__ __align__(16) float g_pool2[NA * 5 * 128];

// CSR over centers (g_count zero-initialized at module load; gather re-zeroes it)
__device__ int g_count[NA];
__device__ int g_off[NA];
__device__ int g_cursor[NA];
__device__ int g_eid[NE];

// CG constants passed by value (2460 B < 4KB param limit)
struct CgParam { float v[615]; };

// ---------------------------------------------------------------------------
// Host-side bit-exact replication of np.random.default_rng(42).normal(...)
// ---------------------------------------------------------------------------
namespace cgen {

typedef unsigned __int128 u128;

struct Pcg64 {
    u128 state, inc;
    uint64_t next() {
        const u128 MUL = (((u128)0x2360ed051fc65da4ULL) << 64) | 0x4385df649fccf645ULL;
        state = state * MUL + inc;
        uint64_t hi = (uint64_t)(state >> 64);
        uint64_t lo = (uint64_t)state;
        uint64_t v  = hi ^ lo;
        unsigned rot = (unsigned)(state >> 122);
        return (v >> rot) | (v << ((64u - rot) & 63u));
    }
    double nextd() { return (double)(next() >> 11) * (1.0 / 9007199254740992.0); }
};

static float    h_cg[615];
static CgParam  h_cgp;

struct Init {
    uint64_t zki[256];
    double   zwi[256], zfi[256];
    Pcg64    g;

    double znorm() {
        const double NOR_R = 3.6541528853610088;
        const double NOR_INV_R = 0.27366123732975828;
        for (;;) {
            uint64_t r = g.next();
            int idx = (int)(r & 0xff);
            r >>= 8;
            int sign = (int)(r & 1);
            uint64_t rabs = (r >> 1) & 0x000fffffffffffffULL;
            double x = (double)rabs * zwi[idx];
            if (sign) x = -x;
            if (rabs < zki[idx]) return x;
            if (idx == 0) {
                double xx, yy;
                do {
                    xx = -NOR_INV_R * std::log1p(-g.nextd());
                    yy = -std::log1p(-g.nextd());
                } while (yy + yy <= xx * xx);
                return ((rabs >> 8) & 1) ? -(NOR_R + xx) : NOR_R + xx;
            } else {
                if ((zfi[idx - 1] - zfi[idx]) * g.nextd() + zfi[idx] <
                    std::exp(-0.5 * x * x))
                    return x;
            }
        }
    }

    Init() {
        // ---- SeedSequence(42), pool_size=4 ----
        uint32_t pool[4];
        uint32_t hc = 0x43b0d7e5u;
        auto hashmix = [&hc](uint32_t v) -> uint32_t {
            v ^= hc; hc *= 0x931e8875u; v *= hc; v ^= v >> 16; return v;
        };
        auto mix = [](uint32_t x, uint32_t y) -> uint32_t {
            uint32_t r = x * 0xca01f9ddu - y * 0x4973f715u; r ^= r >> 16; return r;
        };
        pool[0] = hashmix(42u);
        pool[1] = hashmix(0u);
        pool[2] = hashmix(0u);
        pool[3] = hashmix(0u);
        for (int s = 0; s < 4; s++)
            for (int d = 0; d < 4; d++)
                if (s != d) pool[d] = mix(pool[d], hashmix(pool[s]));

        // ---- generate_state(4, uint64) ----
        uint32_t hc2 = 0x8b51f9ddu;
        uint32_t st32[8];
        for (int i = 0; i < 8; i++) {
            uint32_t v = pool[i & 3];
            v ^= hc2; hc2 *= 0x58f38dedu; v *= hc2; v ^= v >> 16;
            st32[i] = v;
        }
        uint64_t s64[4];
        for (int i = 0; i < 4; i++)
            s64[i] = (uint64_t)st32[2 * i] | ((uint64_t)st32[2 * i + 1] << 32);

        // ---- PCG64 seeding ----
        u128 initstate = (((u128)s64[0]) << 64) | s64[1];
        u128 initseq   = (((u128)s64[2]) << 64) | s64[3];
        const u128 MUL = (((u128)0x2360ed051fc65da4ULL) << 64) | 0x4385df649fccf645ULL;
        g.inc = (initseq << 1) | 1;
        g.state = 0;
        g.state = g.state * MUL + g.inc;
        g.state += initstate;
        g.state = g.state * MUL + g.inc;

        // ---- ziggurat tables ----
        const double r = 3.6541528853610088;
        const double M52 = 4503599627370496.0;
        double f_r = std::exp(-0.5 * r * r);
        double V = r * f_r + 1.2533141373155003 * std::erfc(r * 0.7071067811865476);
        double q = V / f_r;
        zki[0] = (uint64_t)((r / q) * M52);
        zki[1] = 0;
        zwi[0] = q / M52; zwi[255] = r / M52;
        zfi[0] = 1.0;     zfi[255] = f_r;
        double dn = r, tn = r;
        for (int i = 254; i >= 1; i--) {
            dn = std::sqrt(-2.0 * std::log(V / dn + std::exp(-0.5 * dn * dn)));
            zki[i + 1] = (uint64_t)((dn / tn) * M52);
            tn = dn;
            zfi[i] = std::exp(-0.5 * dn * dn);
            zwi[i] = dn / M52;
        }

        // ---- draw all 15 CG tensors in dict order ----
        int pos = 0;
        for (int l1 = 0; l1 <= 2; l1++)
            for (int l2 = 0; l2 <= 2; l2++) {
                int lo = l1 > l2 ? l1 - l2 : l2 - l1;
                int hi = (l1 + l2 < 2) ? (l1 + l2) : 2;
                for (int L = lo; L <= hi; L++) {
                    int n = (2 * l1 + 1) * (2 * l2 + 1) * (2 * L + 1);
                    for (int i = 0; i < n; i++)
                        h_cg[pos++] = (float)(znorm() * 0.3);
                }
            }
        std::memcpy(h_cgp.v, h_cg, sizeof(h_cg));
    }
};
static Init g_init;

} // namespace cgen

// ---------------------------------------------------------------------------
// Packed f32x2 helpers (sm_103a)
// ---------------------------------------------------------------------------
typedef unsigned long long u64p;

__device__ __forceinline__ u64p pk2(float lo, float hi) {
    u64p r; asm("mov.b64 %0,{%1,%2};" : "=l"(r) : "f"(lo), "f"(hi)); return r;
}
__device__ __forceinline__ u64p pdup(float x) { return pk2(x, x); }
__device__ __forceinline__ u64p pmul(u64p a, u64p b) {
    u64p r; asm("mul.rn.f32x2 %0,%1,%2;" : "=l"(r) : "l"(a), "l"(b)); return r;
}
__device__ __forceinline__ void pfma(u64p& c, u64p a, u64p b) {
    asm("fma.rn.f32x2 %0,%1,%2,%0;" : "+l"(c) : "l"(a), "l"(b));
}
__device__ __forceinline__ float hsum(u64p a) {
    float x, y; asm("mov.b64 {%0,%1},%2;" : "=f"(x), "=f"(y) : "l"(a)); return x + y;
}

// ---------------------------------------------------------------------------
// CSR build kernels (zeroing of g_count is done by gather's epilogue)
// ---------------------------------------------------------------------------
__global__ void hist_kernel(const int* __restrict__ centers) {
    int e = blockIdx.x * blockDim.x + threadIdx.x;
    if (e < NE) atomicAdd(&g_count[centers[e]], 1);
}

__global__ void scan_kernel() {
    __shared__ int s[1024];
    const int t = threadIdx.x;
    const int CH = 20;
    int base = t * CH;
    int loc[CH];
    int sum = 0;
#pragma unroll
    for (int i = 0; i < CH; i++) {
        int idx = base + i;
        int c = (idx < NA) ? g_count[idx] : 0;
        loc[i] = sum;
        sum += c;
    }
    s[t] = sum;
    __syncthreads();
    for (int d = 1; d < 1024; d <<= 1) {
        int v = (t >= d) ? s[t - d] : 0;
        __syncthreads();
        s[t] += v;
        __syncthreads();
    }
    int excl = (t == 0) ? 0 : s[t - 1];
#pragma unroll
    for (int i = 0; i < CH; i++) {
        int idx = base + i;
        if (idx < NA) {
            int o = excl + loc[i];
            g_off[idx] = o;
            g_cursor[idx] = o;
        }
    }
}

__global__ void scatter_kernel(const int* __restrict__ centers) {
    int e = blockIdx.x * blockDim.x + threadIdx.x;
    if (e < NE) {
        int p = atomicAdd(&g_cursor[centers[e]], 1);
        g_eid[p] = e;
    }
}

// ---------------------------------------------------------------------------
// Per-edge value bundle (lane-private): 3 radial, 9 feat, 1 sh-lane slot
// ---------------------------------------------------------------------------
struct EVals {
    float shv;              // lane k<9 holds sh value #k for this edge
    float r0, r1, r2;
    float f0, f1[3], f2[5];
};

__device__ __forceinline__ void zero_evals(EVals& v) {
    v.shv = 0.f; v.r0 = 0.f; v.r1 = 0.f; v.r2 = 0.f; v.f0 = 0.f;
#pragma unroll
    for (int a = 0; a < 3; a++) v.f1[a] = 0.f;
#pragma unroll
    for (int a = 0; a < 5; a++) v.f2[a] = 0.f;
}

__device__ __forceinline__ void load_evals(
    EVals& v, int e, int nb, int k,
    const float* __restrict__ radial,
    const float* __restrict__ sh0, const float* __restrict__ sh1,
    const float* __restrict__ sh2,
    const float* __restrict__ feat0, const float* __restrict__ feat1,
    const float* __restrict__ feat2)
{
    v.shv = (k == 0) ? __ldg(sh0 + e)
          : (k < 4)  ? __ldg(sh1 + 3 * e + k - 1)
          : (k < 9)  ? __ldg(sh2 + 5 * e + k - 4) : 0.f;
    v.r0 = __ldg(radial + (size_t)e * KC + k);
    v.r1 = __ldg(radial + (size_t)NE * KC + (size_t)e * KC + k);
    v.r2 = __ldg(radial + 2 * (size_t)NE * KC + (size_t)e * KC + k);
    v.f0 = __ldg(feat0 + (size_t)nb * KC + k);
#pragma unroll
    for (int a = 0; a < 3; a++) v.f1[a] = __ldg(feat1 + ((size_t)nb * 3 + a) * KC + k);
#pragma unroll
    for (int a = 0; a < 5; a++) v.f2[a] = __ldg(feat2 + ((size_t)nb * 5 + a) * KC + k);
}

// ---------------------------------------------------------------------------
// Packed-CG pair table layout (226 float2 entries):
//  O110=0(6)  O112=6(30)  O220=36(15)  O222=51(75)  O011=126(6)  O101=132(6)
//  O121=138(27)  O211=165(30)  O022=195(15)  O202=210(15)  O000=225(1)
// ---------------------------------------------------------------------------
__device__ __forceinline__ void pcg_decode(int u, int& lo, int& hi) {
    lo = -1; hi = -1;
    if (u < 6) {                       // (1,1,0): a*2+j ; cg44 idx a*3+b
        int a = u >> 1, j = u & 1, b0 = 2 * j;
        lo = 44 + a * 3 + b0; if (b0 + 1 < 3) hi = lo + 1;
    } else if (u < 36) {               // (1,1,2): (a*2+j)*5+M ; cg80 idx (a*3+b)*5+M
        int t = u - 6, M = t % 5, aj = t / 5, a = aj >> 1, j = aj & 1, b0 = 2 * j;
        lo = 80 + (a * 3 + b0) * 5 + M; if (b0 + 1 < 3) hi = lo + 5;
    } else if (u < 51) {               // (2,2,0): a*3+j ; cg390 idx a*5+b
        int t = u - 36, a = t / 3, j = t % 3, b0 = 2 * j;
        lo = 390 + a * 5 + b0; if (b0 + 1 < 5) hi = lo + 1;
    } else if (u < 126) {              // (2,2,2): (a*3+j)*5+M ; cg490 idx (a*5+b)*5+M
        int t = u - 51, M = t % 5, aj = t / 5, a = aj / 3, j = aj % 3, b0 = 2 * j;
        lo = 490 + (a * 5 + b0) * 5 + M; if (b0 + 1 < 5) hi = lo + 5;
    } else if (u < 132) {              // (0,1,1): j*3+M ; cg1 idx b*3+M
        int t = u - 126, j = t / 3, M = t % 3, b0 = 2 * j;
        lo = 1 + b0 * 3 + M; if (b0 + 1 < 3) hi = lo + 3;
    } else if (u < 138) {              // (1,0,1): j*3+M ; cg35 idx a*3+M (sum over a)
        int t = u - 132, j = t / 3, M = t % 3, a0 = 2 * j;
        lo = 35 + a0 * 3 + M; if (a0 + 1 < 3) hi = lo + 3;
    } else if (u < 165) {              // (1,2,1): (a*3+j)*3+M ; cg125 idx (a*5+b)*3+M
        int t = u - 138, M = t % 3, aj = t / 3, a = aj / 3, j = aj % 3, b0 = 2 * j;
        lo = 125 + (a * 5 + b0) * 3 + M; if (b0 + 1 < 5) hi = lo + 3;
    } else if (u < 195) {              // (2,1,1): (a*2+j)*3+M ; cg270 idx (a*3+b)*3+M
        int t = u - 165, M = t % 3, aj = t / 3, a = aj >> 1, j = aj & 1, b0 = 2 * j;
        lo = 270 + (a * 3 + b0) * 3 + M; if (b0 + 1 < 3) hi = lo + 3;
    } else if (u < 210) {              // (0,2,2): j*5+M ; cg10 idx b*5+M
        int t = u - 195, j = t / 5, M = t % 5, b0 = 2 * j;
        lo = 10 + b0 * 5 + M; if (b0 + 1 < 5) hi = lo + 5;
    } else if (u < 225) {              // (2,0,2): j*5+M ; cg245 idx a*5+M (sum over a)
        int t = u - 210, j = t / 5, M = t % 5, a0 = 2 * j;
        lo = 245 + a0 * 5 + M; if (a0 + 1 < 5) hi = lo + 5;
    } else {                           // (0,0,0)
        lo = 0;
    }
}

// ---------------------------------------------------------------------------
// Gather kernel: warp = atom, lane = channel k. Packed f32x2 contraction,
// TWO edges per iteration sharing every CG shared-memory load (LDS/edge halved).
// 128-thread blocks (4 atoms), 3 blocks/SM. Index pipeline one pair ahead.
// Epilogue zeroes g_count[atom] for the next call's histogram.
// ---------------------------------------------------------------------------
__global__ void __launch_bounds__(128, 3) gather_kernel(
    CgParam cgp,
    const float* __restrict__ radial,
    const float* __restrict__ sh0, const float* __restrict__ sh1,
    const float* __restrict__ sh2,
    const float* __restrict__ feat0, const float* __restrict__ feat1,
    const float* __restrict__ feat2,
    const int* __restrict__ neighbors)
{
    __shared__ __align__(16) float2 pcg[226];
    for (int u = threadIdx.x; u < 226; u += 128) {
        int lo, hi;
        pcg_decode(u, lo, hi);
        pcg[u] = make_float2(lo >= 0 ? cgp.v[lo] : 0.f,
                             hi >= 0 ? cgp.v[hi] : 0.f);
    }
    __syncthreads();
    const u64p* PC = reinterpret_cast<const u64p*>(pcg);

    const int k = threadIdx.x & 31;
    const int atom = blockIdx.x * 4 + (threadIdx.x >> 5);
    if (atom >= NA) return;

    const int beg = g_off[atom];
    const int end = beg + g_count[atom];

    // packed accumulators (value = lo + hi at the end)
    u64p A00p = 0, A01p = 0, A02p = 0;
    u64p B0p[3], B3p[3], B6p[3], B9p[3];
    u64p C0p[5], C5p[5], C10p[5], C15p[5];
#pragma unroll
    for (int i = 0; i < 3; i++) { B0p[i] = 0; B3p[i] = 0; B6p[i] = 0; B9p[i] = 0; }
#pragma unroll
    for (int i = 0; i < 5; i++) { C0p[i] = 0; C5p[i] = 0; C10p[i] = 0; C15p[i] = 0; }

    // ---- pair index pipeline: indices of the NEXT pair ----
    int eN0 = 0, nbN0 = 0, eN1 = 0, nbN1 = 0;
    EVals curA, curB;
    zero_evals(curA); zero_evals(curB);
    if (beg < end) {
        int e0  = __ldg(g_eid + beg);
        int nb0 = __ldg(neighbors + e0);
        load_evals(curA, e0, nb0, k, radial, sh0, sh1, sh2, feat0, feat1, feat2);
        if (beg + 1 < end) {
            int e1  = __ldg(g_eid + beg + 1);
            int nb1 = __ldg(neighbors + e1);
            load_evals(curB, e1, nb1, k, radial, sh0, sh1, sh2, feat0, feat1, feat2);
        }
        if (beg + 2 < end) { eN0 = __ldg(g_eid + beg + 2); nbN0 = __ldg(neighbors + eN0); }
        if (beg + 3 < end) { eN1 = __ldg(g_eid + beg + 3); nbN1 = __ldg(neighbors + eN1); }
    }

    for (int it = beg; it < end; it += 2) {
        // ---- issue index chain for the pair after next ----
        int eF0 = eN0, nbF0 = nbN0, eF1 = eN1, nbF1 = nbN1;
        if (it + 4 < end) { eF0 = __ldg(g_eid + it + 4); nbF0 = __ldg(neighbors + eF0); }
        if (it + 5 < end) { eF1 = __ldg(g_eid + it + 5); nbF1 = __ldg(neighbors + eF1); }

        // ---- build packed operands for edge A ----
        const float t10A = __shfl_sync(0xffffffffu, curA.shv, 0) * curA.r0;
        float t11A[3], t12A[5];
#pragma unroll
        for (int a = 0; a < 3; a++)
            t11A[a] = __shfl_sync(0xffffffffu, curA.shv, 1 + a) * curA.r1;
#pragma unroll
        for (int a = 0; a < 5; a++)
            t12A[a] = __shfl_sync(0xffffffffu, curA.shv, 4 + a) * curA.r2;
        const u64p T10dA = pdup(t10A), F0dA = pdup(curA.f0);
        const u64p F1p0A = pk2(curA.f1[0], curA.f1[1]), F1p1A = pk2(curA.f1[2], 0.f);
        const u64p F2p0A = pk2(curA.f2[0], curA.f2[1]);
        const u64p F2p1A = pk2(curA.f2[2], curA.f2[3]);
        const u64p F2p2A = pk2(curA.f2[4], 0.f);
        const u64p T11p0A = pk2(t11A[0], t11A[1]), T11p1A = pk2(t11A[2], 0.f);
        const u64p T12p0A = pk2(t12A[0], t12A[1]);
        const u64p T12p1A = pk2(t12A[2], t12A[3]);
        const u64p T12p2A = pk2(t12A[4], 0.f);

        // ---- build packed operands for edge B ----
        const float t10B = __shfl_sync(0xffffffffu, curB.shv, 0) * curB.r0;
        float t11B[3], t12B[5];
#pragma unroll
        for (int a = 0; a < 3; a++)
            t11B[a] = __shfl_sync(0xffffffffu, curB.shv, 1 + a) * curB.r1;
#pragma unroll
        for (int a = 0; a < 5; a++)
            t12B[a] = __shfl_sync(0xffffffffu, curB.shv, 4 + a) * curB.r2;
        const u64p T10dB = pdup(t10B), F0dB = pdup(curB.f0);
        const u64p F1p0B = pk2(curB.f1[0], curB.f1[1]), F1p1B = pk2(curB.f1[2], 0.f);
        const u64p F2p0B = pk2(curB.f2[0], curB.f2[1]);
        const u64p F2p1B = pk2(curB.f2[2], curB.f2[3]);
        const u64p F2p2B = pk2(curB.f2[4], 0.f);
        const u64p T11p0B = pk2(t11B[0], t11B[1]), T11p1B = pk2(t11B[2], 0.f);
        const u64p T12p0B = pk2(t12B[0], t12B[1]);
        const u64p T12p1B = pk2(t12B[2], t12B[3]);
        const u64p T12p2B = pk2(t12B[4], 0.f);

        // ---- load next pair's values (indices prefetched last iteration) ----
        // (issued here so LDGs overlap the FMA body below)
        EVals nA = curA, nB = curB;
        const bool hasA = (it + 2 < end), hasB = (it + 3 < end);
        if (hasA) load_evals(nA, eN0, nbN0, k, radial, sh0, sh1, sh2, feat0, feat1, feat2);
        else      zero_evals(nA);
        if (hasB) load_evals(nB, eN1, nbN1, k, radial, sh0, sh1, sh2, feat0, feat1, feat2);
        else      zero_evals(nB);

        // ================= pair contraction: one PC load, two pfma =========
        // (0,0,0)
        {
            const u64p c = PC[225];
            pfma(A00p, pmul(T10dA, F0dA), c);
            pfma(A00p, pmul(T10dB, F0dB), c);
        }

        // P11 cluster: (1,1,0)->A01, (1,1,2)->C5, (1,2,1)->B6
#pragma unroll
        for (int a = 0; a < 3; a++) {
            const u64p daA = pdup(t11A[a]), daB = pdup(t11B[a]);
            const u64p p0A = pmul(daA, F1p0A), p0B = pmul(daB, F1p0B);
            const u64p p1A = pmul(daA, F1p1A), p1B = pmul(daB, F1p1B);
            { const u64p c = PC[a * 2 + 0]; pfma(A01p, p0A, c); pfma(A01p, p0B, c); }
            { const u64p c = PC[a * 2 + 1]; pfma(A01p, p1A, c); pfma(A01p, p1B, c); }
#pragma unroll
            for (int M = 0; M < 5; M++) {
                const u64p c0 = PC[6 + (a * 2 + 0) * 5 + M];
                pfma(C5p[M], p0A, c0); pfma(C5p[M], p0B, c0);
                const u64p c1 = PC[6 + (a * 2 + 1) * 5 + M];
                pfma(C5p[M], p1A, c1); pfma(C5p[M], p1B, c1);
            }
            const u64p q0A = pmul(daA, F2p0A), q0B = pmul(daB, F2p0B);
            const u64p q1A = pmul(daA, F2p1A), q1B = pmul(daB, F2p1B);
            const u64p q2A = pmul(daA, F2p2A), q2B = pmul(daB, F2p2B);
#pragma unroll
            for (int M = 0; M < 3; M++) {
                const u64p c0 = PC[138 + (a * 3 + 0) * 3 + M];
                pfma(B6p[M], q0A, c0); pfma(B6p[M], q0B, c0);
                const u64p c1 = PC[138 + (a * 3 + 1) * 3 + M];
                pfma(B6p[M], q1A, c1); pfma(B6p[M], q1B, c1);
                const u64p c2 = PC[138 + (a * 3 + 2) * 3 + M];
                pfma(B6p[M], q2A, c2); pfma(B6p[M], q2B, c2);
            }
        }

        // P22 cluster: (2,2,0)->A02, (2,2,2)->C15, (2,1,1)->B9
#pragma unroll
        for (int a = 0; a < 5; a++) {
            const u64p daA = pdup(t12A[a]), daB = pdup(t12B[a]);
            const u64p p0A = pmul(daA, F2p0A), p0B = pmul(daB, F2p0B);
            const u64p p1A = pmul(daA, F2p1A), p1B = pmul(daB, F2p1B);
            const u64p p2A = pmul(daA, F2p2A), p2B = pmul(daB, F2p2B);
            { const u64p c = PC[36 + a * 3 + 0]; pfma(A02p, p0A, c); pfma(A02p, p0B, c); }
            { const u64p c = PC[36 + a * 3 + 1]; pfma(A02p, p1A, c); pfma(A02p, p1B, c); }
            { const u64p c = PC[36 + a * 3 + 2]; pfma(A02p, p2A, c); pfma(A02p, p2B, c); }
#pragma unroll
            for (int M = 0; M < 5; M++) {
                const u64p c0 = PC[51 + (a * 3 + 0) * 5 + M];
                pfma(C15p[M], p0A, c0); pfma(C15p[M], p0B, c0);
                const u64p c1 = PC[51 + (a * 3 + 1) * 5 + M];
                pfma(C15p[M], p1A, c1); pfma(C15p[M], p1B, c1);
                const u64p c2 = PC[51 + (a * 3 + 2) * 5 + M];
                pfma(C15p[M], p2A, c2); pfma(C15p[M], p2B, c2);
            }
            const u64p q0A = pmul(daA, F1p0A), q0B = pmul(daB, F1p0B);
            const u64p q1A = pmul(daA, F1p1A), q1B = pmul(daB, F1p1B);
#pragma unroll
            for (int M = 0; M < 3; M++) {
                const u64p c0 = PC[165 + (a * 2 + 0) * 3 + M];
                pfma(B9p[M], q0A, c0); pfma(B9p[M], q0B, c0);
                const u64p c1 = PC[165 + (a * 2 + 1) * 3 + M];
                pfma(B9p[M], q1A, c1); pfma(B9p[M], q1B, c1);
            }
        }

        // (0,1,1) -> B0
        {
            const u64p p0A = pmul(T10dA, F1p0A), p0B = pmul(T10dB, F1p0B);
            const u64p p1A = pmul(T10dA, F1p1A), p1B = pmul(T10dB, F1p1B);
#pragma unroll
            for (int M = 0; M < 3; M++) {
                const u64p c0 = PC[126 + 0 * 3 + M];
                pfma(B0p[M], p0A, c0); pfma(B0p[M], p0B, c0);
                const u64p c1 = PC[126 + 1 * 3 + M];
                pfma(B0p[M], p1A, c1); pfma(B0p[M], p1B, c1);
            }
        }
        // (1,0,1) -> B3
        {
            const u64p p0A = pmul(T11p0A, F0dA), p0B = pmul(T11p0B, F0dB);
            const u64p p1A = pmul(T11p1A, F0dA), p1B = pmul(T11p1B, F0dB);
#pragma unroll
            for (int M = 0; M < 3; M++) {
                const u64p c0 = PC[132 + 0 * 3 + M];
                pfma(B3p[M], p0A, c0); pfma(B3p[M], p0B, c0);
                const u64p c1 = PC[132 + 1 * 3 + M];
                pfma(B3p[M], p1A, c1); pfma(B3p[M], p1B, c1);
            }
        }
        // (0,2,2) -> C0
        {
            const u64p p0A = pmul(T10dA, F2p0A), p0B = pmul(T10dB, F2p0B);
            const u64p p1A = pmul(T10dA, F2p1A), p1B = pmul(T10dB, F2p1B);
            const u64p p2A = pmul(T10dA, F2p2A), p2B = pmul(T10dB, F2p2B);
#pragma unroll
            for (int M = 0; M < 5; M++) {
                const u64p c0 = PC[195 + 0 * 5 + M];
                pfma(C0p[M], p0A, c0); pfma(C0p[M], p0B, c0);
                const u64p c1 = PC[195 + 1 * 5 + M];
                pfma(C0p[M], p1A, c1); pfma(C0p[M], p1B, c1);
                const u64p c2 = PC[195 + 2 * 5 + M];
                pfma(C0p[M], p2A, c2); pfma(C0p[M], p2B, c2);
            }
        }
        // (2,0,2) -> C10
        {
            const u64p p0A = pmul(T12p0A, F0dA), p0B = pmul(T12p0B, F0dB);
            const u64p p1A = pmul(T12p1A, F0dA), p1B = pmul(T12p1B, F0dB);
            const u64p p2A = pmul(T12p2A, F0dA), p2B = pmul(T12p2B, F0dB);
#pragma unroll
            for (int M = 0; M < 5; M++) {
                const u64p c0 = PC[210 + 0 * 5 + M];
                pfma(C10p[M], p0A, c0); pfma(C10p[M], p0B, c0);
                const u64p c1 = PC[210 + 1 * 5 + M];
                pfma(C10p[M], p1A, c1); pfma(C10p[M], p1B, c1);
                const u64p c2 = PC[210 + 2 * 5 + M];
                pfma(C10p[M], p2A, c2); pfma(C10p[M], p2B, c2);
            }
        }

        // ---- rotate pipeline ----
        curA = nA; curB = nB;
        eN0 = eF0; nbN0 = nbF0; eN1 = eF1; nbN1 = nbF1;
    }

    // ---- write pooled rows (coalesced, no atomics) ----
    float* p0 = g_pool0 + (size_t)atom * 96 + k;
    p0[0]  = hsum(A00p);
    p0[32] = hsum(A01p);
    p0[64] = hsum(A02p);

    float* p1 = g_pool1 + (size_t)atom * 384 + k;
#pragma unroll
    for (int M = 0; M < 3; M++) {
        p1[M * 128 + 0]  = hsum(B0p[M]);
        p1[M * 128 + 32] = hsum(B3p[M]);
        p1[M * 128 + 64] = hsum(B6p[M]);
        p1[M * 128 + 96] = hsum(B9p[M]);
    }

    float* p2 = g_pool2 + (size_t)atom * 640 + k;
#pragma unroll
    for (int M = 0; M < 5; M++) {
        p2[M * 128 + 0]  = hsum(C0p[M]);
        p2[M * 128 + 32] = hsum(C5p[M]);
        p2[M * 128 + 64] = hsum(C10p[M]);
        p2[M * 128 + 96] = hsum(C15p[M]);
    }

    // re-zero count for the next call's histogram
    if (k == 0) g_count[atom] = 0;
}

// ---------------------------------------------------------------------------
// Atom kernel: per-atom linear + bias, *0.1, + residual feat.
// Loop interchange: each weight float4 (LDS) is reused across 4 atoms.
// ---------------------------------------------------------------------------
__global__ void __launch_bounds__(288) atom_kernel(
    const float* __restrict__ feat0, const float* __restrict__ feat1,
    const float* __restrict__ feat2,
    const float* __restrict__ W0, const float* __restrict__ b0,
    const float* __restrict__ W1, const float* __restrict__ b1,
    const float* __restrict__ W2, const float* __restrict__ b2,
    float* __restrict__ out)
{
    __shared__ __align__(16) float wt0[32 * 100];
    __shared__ __align__(16) float wt1[32 * 132];
    __shared__ __align__(16) float wt2[32 * 132];
    __shared__ float bsh[96];

    for (int i = threadIdx.x; i < 96 * 32; i += 288)
        wt0[(i & 31) * 100 + (i >> 5)] = W0[i];
    for (int i = threadIdx.x; i < 128 * 32; i += 288)
        wt1[(i & 31) * 132 + (i >> 5)] = W1[i];
    for (int i = threadIdx.x; i < 128 * 32; i += 288)
        wt2[(i & 31) * 132 + (i >> 5)] = W2[i];
    if (threadIdx.x < 32) {
        bsh[threadIdx.x]      = b0[threadIdx.x];
        bsh[32 + threadIdx.x] = b1[threadIdx.x];
        bsh[64 + threadIdx.x] = b2[threadIdx.x];
    }
    __syncthreads();

    const int w = threadIdx.x >> 5;
    const int k = threadIdx.x & 31;

    for (int g = blockIdx.x; g < NA / 4; g += gridDim.x) {
        const int a0 = g * 4;
        float acc[4] = {0.f, 0.f, 0.f, 0.f};
        if (w == 0) {
            const float4* wr = reinterpret_cast<const float4*>(wt0 + k * 100);
#pragma unroll
            for (int j = 0; j < 24; j++) {
                const float4 wv = wr[j];
#pragma unroll
                for (int t = 0; t < 4; t++) {
                    const float4 p = __ldg(reinterpret_cast<const float4*>(
                        g_pool0 + (size_t)(a0 + t) * 96) + j);
                    acc[t] += p.x * wv.x + p.y * wv.y + p.z * wv.z + p.w * wv.w;
                }
            }
#pragma unroll
            for (int t = 0; t < 4; t++) {
                const int o = (a0 + t) * 32 + k;
                out[o] = (acc[t] + bsh[k]) * 0.1f + __ldg(feat0 + o);
            }
        } else if (w <= 3) {
            const int M = w - 1;
            const float4* wr = reinterpret_cast<const float4*>(wt1 + k * 132);
#pragma unroll
            for (int j = 0; j < 32; j++) {
                const float4 wv = wr[j];
#pragma unroll
                for (int t = 0; t < 4; t++) {
                    const float4 p = __ldg(reinterpret_cast<const float4*>(
                        g_pool1 + ((size_t)(a0 + t) * 3 + M) * 128) + j);
                    acc[t] += p.x * wv.x + p.y * wv.y + p.z * wv.z + p.w * wv.w;
                }
            }
#pragma unroll
            for (int t = 0; t < 4; t++) {
                const int o = ((a0 + t) * 3 + M) * 32 + k;
                out[NA * 32 + o] = (acc[t] + bsh[32 + k]) * 0.1f + __ldg(feat1 + o);
            }
        } else {
            const int M = w - 4;
            const float4* wr = reinterpret_cast<const float4*>(wt2 + k * 132);
#pragma unroll
            for (int j = 0; j < 32; j++) {
                const float4 wv = wr[j];
#pragma unroll
                for (int t = 0; t < 4; t++) {
                    const float4 p = __ldg(reinterpret_cast<const float4*>(
                        g_pool2 + ((size_t)(a0 + t) * 5 + M) * 128) + j);
                    acc[t] += p.x * wv.x + p.y * wv.y + p.z * wv.z + p.w * wv.w;
                }
            }
#pragma unroll
            for (int t = 0; t < 4; t++) {
                const int o = ((a0 + t) * 5 + M) * 32 + k;
                out[NA * 32 + NA * 96 + o] = (acc[t] + bsh[64 + k]) * 0.1f + __ldg(feat2 + o);
            }
        }
    }
}

// ---------------------------------------------------------------------------
// Launcher
// ---------------------------------------------------------------------------
extern "C" void kernel_launch(void* const* d_in, const int* in_sizes, int n_in,
                              void* d_out, int out_size) {
    (void)in_sizes; (void)n_in; (void)out_size;
    const float* radial = (const float*)d_in[0];
    const float* sh0    = (const float*)d_in[1];
    const float* sh1    = (const float*)d_in[2];
    const float* sh2    = (const float*)d_in[3];
    const float* feat0  = (const float*)d_in[4];
    const float* feat1  = (const float*)d_in[5];
    const float* feat2  = (const float*)d_in[6];
    const float* W0     = (const float*)d_in[7];
    const float* b0     = (const float*)d_in[8];
    const float* W1     = (const float*)d_in[9];
    const float* b1     = (const float*)d_in[10];
    const float* W2     = (const float*)d_in[11];
    const float* b2     = (const float*)d_in[12];
    const int* centers   = (const int*)d_in[13];
    const int* neighbors = (const int*)d_in[14];
    float* out = (float*)d_out;

    // CSR build over centers (g_count pre-zeroed by previous gather / static init)
    hist_kernel<<<(NE + 255) / 256, 256>>>(centers);
    scan_kernel<<<1, 1024>>>();
    scatter_kernel<<<(NE + 255) / 256, 256>>>(centers);

    // gather: warp per atom, packed f32x2 contraction, 2 edges/iter sharing CG LDS
    gather_kernel<<<NA / 4, 128>>>(cgen::h_cgp, radial, sh0, sh1, sh2,
                                   feat0, feat1, feat2, neighbors);

    // atom GEMM: weight reuse across 4 atoms
    atom_kernel<<<1250, 288>>>(feat0, feat1, feat2,
                               W0, b0, W1, b1, W2, b2, out);
}

// round 17
// speedup vs baseline: 1.3300x; 1.2578x over previous
#include <cuda_runtime.h>
#include <cstdint>
#include <cstring>
#include <cmath>

#define NE 200000
#define NA 20000
#define KC 32

// ---------------------------------------------------------------------------
// Pooled scratch (concat layout): L0 [NA][1][96], L1 [NA][3][128], L2 [NA][5][128]
// ---------------------------------------------------------------------------
__device__ __align__(16) float g_pool0[NA * 96];
__device__ __align__(16) float g_pool1[NA * 3 * 128];
__device__ __align__(16) float g_pool2[NA * 5 * 128];

// CSR over centers (g_count zero-initialized at module load; gather re-zeroes it)
__device__ int g_count[NA];
__device__ int g_off[NA];
__device__ int g_cursor[NA];
__device__ int g_eid[NE];

// ---------------------------------------------------------------------------
// COMPILE-TIME bit-exact replication of np.random.default_rng(42).normal(...)
// All CG coefficients become immediate literals in SASS (FFMA-imm, rt=1).
// ---------------------------------------------------------------------------
typedef unsigned __int128 u128c;

struct CgArr { float v[615]; };

// ---- constexpr double math (accuracy ~1e-14..1e-12, far beyond need) ----
constexpr double c_sqrt(double x) {
    if (x <= 0.0) return 0.0;
    double y = x > 1.0 ? x : 1.0;
    for (int i = 0; i < 48; i++) y = 0.5 * (y + x / y);
    return y;
}

constexpr double c_exp(double x) {
    const double LN2 = 0.69314718055994530942;
    double qd = x / LN2;
    int n = (int)qd;
    if (qd < 0.0 && (double)n != qd) n -= 1;          // floor
    double r = x - (double)n * LN2;                    // r in [0, ln2)
    if (r > 0.34657359027997265) { r -= LN2; n += 1; } // center
    double s = 1.0, term = 1.0;
    for (int i = 1; i <= 26; i++) { term *= r / (double)i; s += term; }
    double p = 1.0;
    int m = n < 0 ? -n : n;
    for (int i = 0; i < m; i++) p *= (n < 0 ? 0.5 : 2.0);
    return s * p;
}

constexpr double c_log(double x) {
    const double LN2 = 0.69314718055994530942;
    int k = 0; double m = x;
    while (m < 0.70710678118654752) { m *= 2.0; k -= 1; }
    while (m > 1.41421356237309515) { m *= 0.5; k += 1; }
    double t = (m - 1.0) / (m + 1.0);
    double t2 = t * t, p = t, s = 0.0;
    for (int i = 0; i < 30; i++) { s += p / (double)(2 * i + 1); p *= t2; }
    return 2.0 * s + (double)k * LN2;
}

constexpr double c_erfc(double x) {          // via erf Taylor (x ~ 2.58)
    double x2 = x * x;
    double term = x;                          // x^(2k+1)/k!
    double sum = 0.0;
    for (int k = 0; k < 90; k++) {
        double contrib = term / (double)(2 * k + 1);
        sum += (k & 1) ? -contrib : contrib;
        term *= x2 / (double)(k + 1);
    }
    return 1.0 - 1.1283791670955125739 * sum; // 2/sqrt(pi)
}

constexpr unsigned c_hashmix(unsigned v, unsigned& hc) {
    v ^= hc; hc *= 0x931e8875u; v *= hc; v ^= v >> 16; return v;
}
constexpr unsigned c_mix(unsigned x, unsigned y) {
    unsigned r = x * 0xca01f9ddu - y * 0x4973f715u; r ^= r >> 16; return r;
}

constexpr CgArr cg_gen() {
    // ---- SeedSequence(42), pool_size=4 ----
    unsigned hc = 0x43b0d7e5u;
    unsigned pool[4] = {};
    pool[0] = c_hashmix(42u, hc);
    pool[1] = c_hashmix(0u, hc);
    pool[2] = c_hashmix(0u, hc);
    pool[3] = c_hashmix(0u, hc);
    for (int s = 0; s < 4; s++)
        for (int d = 0; d < 4; d++)
            if (s != d) pool[d] = c_mix(pool[d], c_hashmix(pool[s], hc));

    // ---- generate_state(4, uint64) ----
    unsigned hc2 = 0x8b51f9ddu;
    unsigned st32[8] = {};
    for (int i = 0; i < 8; i++) {
        unsigned v = pool[i & 3];
        v ^= hc2; hc2 *= 0x58f38dedu; v *= hc2; v ^= v >> 16;
        st32[i] = v;
    }
    unsigned long long s64[4] = {};
    for (int i = 0; i < 4; i++)
        s64[i] = (unsigned long long)st32[2 * i] |
                 ((unsigned long long)st32[2 * i + 1] << 32);

    // ---- PCG64 seeding ----
    const u128c MUL = (((u128c)0x2360ed051fc65da4ULL) << 64) | 0x4385df649fccf645ULL;
    u128c inc = ((((u128c)s64[2]) << 64 | s64[3]) << 1) | 1;
    u128c state = 0;
    state = state * MUL + inc;
    state += (((u128c)s64[0]) << 64) | s64[1];
    state = state * MUL + inc;

    // ---- ziggurat tables ----
    double zwi[256] = {}, zfi[256] = {};
    unsigned long long zki[256] = {};
    const double r = 3.6541528853610088;
    const double M52 = 4503599627370496.0;
    double f_r = c_exp(-0.5 * r * r);
    double V = r * f_r + 1.2533141373155003 * c_erfc(r * 0.7071067811865476);
    double q = V / f_r;
    zki[0] = (unsigned long long)((r / q) * M52);
    zki[1] = 0;
    zwi[0] = q / M52; zwi[255] = r / M52;
    zfi[0] = 1.0;     zfi[255] = f_r;
    double dn = r, tn = r;
    for (int i = 254; i >= 1; i--) {
        dn = c_sqrt(-2.0 * c_log(V / dn + c_exp(-0.5 * dn * dn)));
        zki[i + 1] = (unsigned long long)((dn / tn) * M52);
        tn = dn;
        zfi[i] = c_exp(-0.5 * dn * dn);
        zwi[i] = dn / M52;
    }

    // ---- draw all 15 CG tensors in dict order ----
    CgArr out{};
    int pos = 0;
    for (int l1 = 0; l1 <= 2; l1++)
        for (int l2 = 0; l2 <= 2; l2++) {
            int lo = l1 > l2 ? l1 - l2 : l2 - l1;
            int hi = (l1 + l2 < 2) ? (l1 + l2) : 2;
            for (int L = lo; L <= hi; L++) {
                int n = (2 * l1 + 1) * (2 * l2 + 1) * (2 * L + 1);
                for (int i = 0; i < n; i++) {
                    double val = 0.0; bool done = false;
                    while (!done) {
                        state = state * MUL + inc;
                        unsigned long long hi64 = (unsigned long long)(state >> 64);
                        unsigned long long lo64 = (unsigned long long)state;
                        unsigned long long vx = hi64 ^ lo64;
                        unsigned rot = (unsigned)(state >> 122);
                        unsigned long long rr =
                            (vx >> rot) | (vx << ((64u - rot) & 63u));
                        int idx = (int)(rr & 0xff);
                        rr >>= 8;
                        int sign = (int)(rr & 1);
                        unsigned long long rabs = (rr >> 1) & 0x000fffffffffffffULL;
                        double x = (double)rabs * zwi[idx];
                        if (sign) x = -x;
                        if (rabs < zki[idx]) { val = x; done = true; }
                        else if (idx == 0) {
                            const double NOR_R = 3.6541528853610088;
                            const double NOR_INV_R = 0.27366123732975828;
                            double xx = 0.0, yy = 0.0;
                            do {
                                state = state * MUL + inc;
                                unsigned long long h1 = (unsigned long long)(state >> 64);
                                unsigned long long l1v = (unsigned long long)state;
                                unsigned long long v1 = h1 ^ l1v;
                                unsigned ro1 = (unsigned)(state >> 122);
                                unsigned long long r1 =
                                    (v1 >> ro1) | (v1 << ((64u - ro1) & 63u));
                                double d1 = (double)(r1 >> 11) * (1.0 / 9007199254740992.0);
                                xx = -NOR_INV_R * c_log(1.0 - d1);
                                state = state * MUL + inc;
                                unsigned long long h2 = (unsigned long long)(state >> 64);
                                unsigned long long l2v = (unsigned long long)state;
                                unsigned long long v2 = h2 ^ l2v;
                                unsigned ro2 = (unsigned)(state >> 122);
                                unsigned long long r2 =
                                    (v2 >> ro2) | (v2 << ((64u - ro2) & 63u));
                                double d2 = (double)(r2 >> 11) * (1.0 / 9007199254740992.0);
                                yy = -c_log(1.0 - d2);
                            } while (yy + yy <= xx * xx);
                            val = ((rabs >> 8) & 1) ? -(NOR_R + xx) : NOR_R + xx;
                            done = true;
                        } else {
                            state = state * MUL + inc;
                            unsigned long long h3 = (unsigned long long)(state >> 64);
                            unsigned long long l3v = (unsigned long long)state;
                            unsigned long long v3 = h3 ^ l3v;
                            unsigned ro3 = (unsigned)(state >> 122);
                            unsigned long long r3 =
                                (v3 >> ro3) | (v3 << ((64u - ro3) & 63u));
                            double d3 = (double)(r3 >> 11) * (1.0 / 9007199254740992.0);
                            if ((zfi[idx - 1] - zfi[idx]) * d3 + zfi[idx] <
                                c_exp(-0.5 * x * x)) { val = x; done = true; }
                        }
                    }
                    out.v[pos++] = (float)(val * 0.3);
                }
            }
        }
    return out;
}

__device__ constexpr CgArr CG = cg_gen();

// ---------------------------------------------------------------------------
// Template-folded contraction: all CG indices are compile-time -> FFMA-imm.
//   acc[M] += p * CG[BASE + M]          (fma_m)
//   for a,b: p = t[a]*f[b]; acc[M] += p*CG[BASE + (a*NB+b)*NM + M]  (path_ab)
// ---------------------------------------------------------------------------
template <int NM, int BASE, int M = 0>
__device__ __forceinline__ void fma_m(float* acc, float p) {
    if constexpr (M < NM) {
        acc[M] = fmaf(p, CG.v[BASE + M], acc[M]);
        fma_m<NM, BASE, M + 1>(acc, p);
    }
}

template <int NAa, int NBb, int NM, int BASE, int A = 0, int B = 0>
__device__ __forceinline__ void path_ab(const float* t, const float* f, float* acc) {
    if constexpr (A < NAa) {
        if constexpr (B < NBb) {
            float p = t[A] * f[B];
            fma_m<NM, BASE + (A * NBb + B) * NM>(acc, p);
            path_ab<NAa, NBb, NM, BASE, A, B + 1>(t, f, acc);
        } else {
            path_ab<NAa, NBb, NM, BASE, A + 1, 0>(t, f, acc);
        }
    }
}

// ---------------------------------------------------------------------------
// CSR build kernels (zeroing of g_count is done by gather's epilogue)
// ---------------------------------------------------------------------------
__global__ void hist_kernel(const int* __restrict__ centers) {
    int e = blockIdx.x * blockDim.x + threadIdx.x;
    if (e < NE) atomicAdd(&g_count[centers[e]], 1);
}

__global__ void scan_kernel() {
    __shared__ int s[1024];
    const int t = threadIdx.x;
    const int CH = 20;
    int base = t * CH;
    int loc[CH];
    int sum = 0;
#pragma unroll
    for (int i = 0; i < CH; i++) {
        int idx = base + i;
        int c = (idx < NA) ? g_count[idx] : 0;
        loc[i] = sum;
        sum += c;
    }
    s[t] = sum;
    __syncthreads();
    for (int d = 1; d < 1024; d <<= 1) {
        int v = (t >= d) ? s[t - d] : 0;
        __syncthreads();
        s[t] += v;
        __syncthreads();
    }
    int excl = (t == 0) ? 0 : s[t - 1];
#pragma unroll
    for (int i = 0; i < CH; i++) {
        int idx = base + i;
        if (idx < NA) {
            int o = excl + loc[i];
            g_off[idx] = o;
            g_cursor[idx] = o;
        }
    }
}

__global__ void scatter_kernel(const int* __restrict__ centers) {
    int e = blockIdx.x * blockDim.x + threadIdx.x;
    if (e < NE) {
        int p = atomicAdd(&g_cursor[centers[e]], 1);
        g_eid[p] = e;
    }
}

// ---------------------------------------------------------------------------
// Per-edge value bundle (lane-private): 3 radial, 9 feat, 1 sh-lane slot
// ---------------------------------------------------------------------------
struct EVals {
    float shv;
    float r0, r1, r2;
    float f0, f1[3], f2[5];
};

__device__ __forceinline__ void load_evals(
    EVals& v, int e, int nb, int k,
    const float* __restrict__ radial,
    const float* __restrict__ sh0, const float* __restrict__ sh1,
    const float* __restrict__ sh2,
    const float* __restrict__ feat0, const float* __restrict__ feat1,
    const float* __restrict__ feat2)
{
    v.shv = (k == 0) ? __ldg(sh0 + e)
          : (k < 4)  ? __ldg(sh1 + 3 * e + k - 1)
          : (k < 9)  ? __ldg(sh2 + 5 * e + k - 4) : 0.f;
    v.r0 = __ldg(radial + (size_t)e * KC + k);
    v.r1 = __ldg(radial + (size_t)NE * KC + (size_t)e * KC + k);
    v.r2 = __ldg(radial + 2 * (size_t)NE * KC + (size_t)e * KC + k);
    v.f0 = __ldg(feat0 + (size_t)nb * KC + k);
#pragma unroll
    for (int a = 0; a < 3; a++) v.f1[a] = __ldg(feat1 + ((size_t)nb * 3 + a) * KC + k);
#pragma unroll
    for (int a = 0; a < 5; a++) v.f2[a] = __ldg(feat2 + ((size_t)nb * 5 + a) * KC + k);
}

// ---------------------------------------------------------------------------
// Gather kernel: warp = atom, lane = channel k. CG as SASS immediates
// (FFMA-imm rt=1, zero CG memory traffic). 128-thread blocks (4 atoms).
// 2-deep index pipeline + 1-deep value prefetch; sh via shuffle broadcast.
// ---------------------------------------------------------------------------
__global__ void __launch_bounds__(128) gather_kernel(
    const float* __restrict__ radial,
    const float* __restrict__ sh0, const float* __restrict__ sh1,
    const float* __restrict__ sh2,
    const float* __restrict__ feat0, const float* __restrict__ feat1,
    const float* __restrict__ feat2,
    const int* __restrict__ neighbors)
{
    const int k = threadIdx.x & 31;
    const int atom = blockIdx.x * 4 + (threadIdx.x >> 5);
    if (atom >= NA) return;

    const int beg = g_off[atom];
    const int end = beg + g_count[atom];

    float A[3] = {0.f, 0.f, 0.f};
    float B[12], C[20];
#pragma unroll
    for (int i = 0; i < 12; i++) B[i] = 0.f;
#pragma unroll
    for (int i = 0; i < 20; i++) C[i] = 0.f;

    // ---- pipeline prologue ----
    int e1 = 0, nb1 = 0;
    EVals cur;
    if (beg < end) {
        int e0  = __ldg(g_eid + beg);
        int nb0 = __ldg(neighbors + e0);
        load_evals(cur, e0, nb0, k, radial, sh0, sh1, sh2, feat0, feat1, feat2);
        if (beg + 1 < end) {
            e1  = __ldg(g_eid + beg + 1);
            nb1 = __ldg(neighbors + e1);
        }
    }

    for (int it = beg; it < end; it++) {
        // index chain for it+2
        int e2 = e1, nb2 = nb1;
        if (it + 2 < end) {
            e2  = __ldg(g_eid + it + 2);
            nb2 = __ldg(neighbors + e2);
        }
        // value prefetch for it+1
        EVals nxt = cur;
        if (it + 1 < end)
            load_evals(nxt, e1, nb1, k, radial, sh0, sh1, sh2, feat0, feat1, feat2);

        // broadcast sh, build t vectors
        float t10a[1];
        t10a[0] = __shfl_sync(0xffffffffu, cur.shv, 0) * cur.r0;
        float t11[3], t12[5];
#pragma unroll
        for (int a = 0; a < 3; a++)
            t11[a] = __shfl_sync(0xffffffffu, cur.shv, 1 + a) * cur.r1;
#pragma unroll
        for (int a = 0; a < 5; a++)
            t12[a] = __shfl_sync(0xffffffffu, cur.shv, 4 + a) * cur.r2;
        float f0a[1]; f0a[0] = cur.f0;

        // ---- 11 even-parity CG paths, coefficients folded to immediates ----
        path_ab<1, 1, 1, 0>(t10a, f0a, A + 0);        // (0,0,0)
        path_ab<3, 3, 1, 44>(t11, cur.f1, A + 1);     // (1,1,0)
        path_ab<5, 5, 1, 390>(t12, cur.f2, A + 2);    // (2,2,0)
        path_ab<1, 3, 3, 1>(t10a, cur.f1, B + 0);     // (0,1,1)
        path_ab<3, 1, 3, 35>(t11, f0a, B + 3);        // (1,0,1)
        path_ab<3, 5, 3, 125>(t11, cur.f2, B + 6);    // (1,2,1)
        path_ab<5, 3, 3, 270>(t12, cur.f1, B + 9);    // (2,1,1)
        path_ab<1, 5, 5, 10>(t10a, cur.f2, C + 0);    // (0,2,2)
        path_ab<3, 3, 5, 80>(t11, cur.f1, C + 5);     // (1,1,2)
        path_ab<5, 1, 5, 245>(t12, f0a, C + 10);      // (2,0,2)
        path_ab<5, 5, 5, 490>(t12, cur.f2, C + 15);   // (2,2,2)

        // rotate pipeline
        cur = nxt;
        e1 = e2; nb1 = nb2;
    }

    // ---- write pooled rows (coalesced, no atomics) ----
    float* p0 = g_pool0 + (size_t)atom * 96 + k;
    p0[0]  = A[0];
    p0[32] = A[1];
    p0[64] = A[2];

    float* p1 = g_pool1 + (size_t)atom * 384 + k;
#pragma unroll
    for (int M = 0; M < 3; M++) {
        p1[M * 128 + 0]  = B[0 + M];
        p1[M * 128 + 32] = B[3 + M];
        p1[M * 128 + 64] = B[6 + M];
        p1[M * 128 + 96] = B[9 + M];
    }

    float* p2 = g_pool2 + (size_t)atom * 640 + k;
#pragma unroll
    for (int M = 0; M < 5; M++) {
        p2[M * 128 + 0]  = C[0 + M];
        p2[M * 128 + 32] = C[5 + M];
        p2[M * 128 + 64] = C[10 + M];
        p2[M * 128 + 96] = C[15 + M];
    }

    // re-zero count for the next call's histogram
    if (k == 0) g_count[atom] = 0;
}

// ---------------------------------------------------------------------------
// Atom kernel: per-atom linear + bias, *0.1, + residual feat.
// Loop interchange: each weight float4 (LDS) is reused across 4 atoms.
// ---------------------------------------------------------------------------
__global__ void __launch_bounds__(288) atom_kernel(
    const float* __restrict__ feat0, const float* __restrict__ feat1,
    const float* __restrict__ feat2,
    const float* __restrict__ W0, const float* __restrict__ b0,
    const float* __restrict__ W1, const float* __restrict__ b1,
    const float* __restrict__ W2, const float* __restrict__ b2,
    float* __restrict__ out)
{
    __shared__ __align__(16) float wt0[32 * 100];
    __shared__ __align__(16) float wt1[32 * 132];
    __shared__ __align__(16) float wt2[32 * 132];
    __shared__ float bsh[96];

    for (int i = threadIdx.x; i < 96 * 32; i += 288)
        wt0[(i & 31) * 100 + (i >> 5)] = W0[i];
    for (int i = threadIdx.x; i < 128 * 32; i += 288)
        wt1[(i & 31) * 132 + (i >> 5)] = W1[i];
    for (int i = threadIdx.x; i < 128 * 32; i += 288)
        wt2[(i & 31) * 132 + (i >> 5)] = W2[i];
    if (threadIdx.x < 32) {
        bsh[threadIdx.x]      = b0[threadIdx.x];
        bsh[32 + threadIdx.x] = b1[threadIdx.x];
        bsh[64 + threadIdx.x] = b2[threadIdx.x];
    }
    __syncthreads();

    const int w = threadIdx.x >> 5;
    const int k = threadIdx.x & 31;

    for (int g = blockIdx.x; g < NA / 4; g += gridDim.x) {
        const int a0 = g * 4;
        float acc[4] = {0.f, 0.f, 0.f, 0.f};
        if (w == 0) {
            const float4* wr = reinterpret_cast<const float4*>(wt0 + k * 100);
#pragma unroll
            for (int j = 0; j < 24; j++) {
                const float4 wv = wr[j];
#pragma unroll
                for (int t = 0; t < 4; t++) {
                    const float4 p = __ldg(reinterpret_cast<const float4*>(
                        g_pool0 + (size_t)(a0 + t) * 96) + j);
                    acc[t] += p.x * wv.x + p.y * wv.y + p.z * wv.z + p.w * wv.w;
                }
            }
#pragma unroll
            for (int t = 0; t < 4; t++) {
                const int o = (a0 + t) * 32 + k;
                out[o] = (acc[t] + bsh[k]) * 0.1f + __ldg(feat0 + o);
            }
        } else if (w <= 3) {
            const int M = w - 1;
            const float4* wr = reinterpret_cast<const float4*>(wt1 + k * 132);
#pragma unroll
            for (int j = 0; j < 32; j++) {
                const float4 wv = wr[j];
#pragma unroll
                for (int t = 0; t < 4; t++) {
                    const float4 p = __ldg(reinterpret_cast<const float4*>(
                        g_pool1 + ((size_t)(a0 + t) * 3 + M) * 128) + j);
                    acc[t] += p.x * wv.x + p.y * wv.y + p.z * wv.z + p.w * wv.w;
                }
            }
#pragma unroll
            for (int t = 0; t < 4; t++) {
                const int o = ((a0 + t) * 3 + M) * 32 + k;
                out[NA * 32 + o] = (acc[t] + bsh[32 + k]) * 0.1f + __ldg(feat1 + o);
            }
        } else {
            const int M = w - 4;
            const float4* wr = reinterpret_cast<const float4*>(wt2 + k * 132);
#pragma unroll
            for (int j = 0; j < 32; j++) {
                const float4 wv = wr[j];
#pragma unroll
                for (int t = 0; t < 4; t++) {
                    const float4 p = __ldg(reinterpret_cast<const float4*>(
                        g_pool2 + ((size_t)(a0 + t) * 5 + M) * 128) + j);
                    acc[t] += p.x * wv.x + p.y * wv.y + p.z * wv.z + p.w * wv.w;
                }
            }
#pragma unroll
            for (int t = 0; t < 4; t++) {
                const int o = ((a0 + t) * 5 + M) * 32 + k;
                out[NA * 32 + NA * 96 + o] = (acc[t] + bsh[64 + k]) * 0.1f + __ldg(feat2 + o);
            }
        }
    }
}

// ---------------------------------------------------------------------------
// Launcher
// ---------------------------------------------------------------------------
extern "C" void kernel_launch(void* const* d_in, const int* in_sizes, int n_in,
                              void* d_out, int out_size) {
    (void)in_sizes; (void)n_in; (void)out_size;
    const float* radial = (const float*)d_in[0];
    const float* sh0    = (const float*)d_in[1];
    const float* sh1    = (const float*)d_in[2];
    const float* sh2    = (const float*)d_in[3];
    const float* feat0  = (const float*)d_in[4];
    const float* feat1  = (const float*)d_in[5];
    const float* feat2  = (const float*)d_in[6];
    const float* W0     = (const float*)d_in[7];
    const float* b0     = (const float*)d_in[8];
    const float* W1     = (const float*)d_in[9];
    const float* b1     = (const float*)d_in[10];
    const float* W2     = (const float*)d_in[11];
    const float* b2     = (const float*)d_in[12];
    const int* centers   = (const int*)d_in[13];
    const int* neighbors = (const int*)d_in[14];
    float* out = (float*)d_out;

    // CSR build over centers (g_count pre-zeroed by previous gather / static init)
    hist_kernel<<<(NE + 255) / 256, 256>>>(centers);
    scan_kernel<<<1, 1024>>>();
    scatter_kernel<<<(NE + 255) / 256, 256>>>(centers);

    // gather: warp per atom, CG as SASS immediates
    gather_kernel<<<NA / 4, 128>>>(radial, sh0, sh1, sh2,
                                   feat0, feat1, feat2, neighbors);

    // atom GEMM: weight reuse across 4 atoms
    atom_kernel<<<1250, 288>>>(feat0, feat1, feat2,
                               W0, b0, W1, b1, W2, b2, out);
}